// round 9
// baseline (speedup 1.0000x reference)
#include <cuda_runtime.h>
#include <cuda_bf16.h>
#include <cstdint>

#define BATCH   32768
#define NSTEPS  3
#define BN_EPS  1e-5f
#define FULLM   0xffffffffu

// ---------------- SMEM layout (byte offsets, 1024-aligned) ----------------
#define OFF_A    0        // masked_x bf16: hi 32768 + lo 32768
#define OFF_H    65536    // h1 bf16: hi 49152 + lo 49152
#define OFF_B    163840   // B tile image (hi+lo), up to 49152
#define OFF_TAU  212992   // 128 floats
#define SMEM_BYTES 213504

// ---------------- device scratch ----------------
__device__ float g_sum[128];
__device__ float g_sumsq[128];
__device__ float g_mloss;
__device__ float g_xn[(size_t)BATCH * 128];
__device__ float g_att[(size_t)BATCH * 128];
__device__ __align__(16) __nv_bfloat16 g_wb[1032192];   // pre-swizzled hi/lo weight images

#define WB_E0 0
#define WB_D0 294912
#define WB_E1 589824
#define WB_D1 884736

// ---------------- helpers ----------------
__device__ __forceinline__ float wsum(float v) {
#pragma unroll
    for (int o = 16; o > 0; o >>= 1) v += __shfl_xor_sync(FULLM, v, o);
    return v;
}
__device__ __forceinline__ float wmax(float v) {
#pragma unroll
    for (int o = 16; o > 0; o >>= 1) v = fmaxf(v, __shfl_xor_sync(FULLM, v, o));
    return v;
}
__device__ __forceinline__ float sigf(float x) { return 1.0f / (1.0f + __expf(-x)); }

__device__ __forceinline__ uint32_t smem_to_u32(const void* p) {
    uint32_t a;
    asm("{ .reg .u64 t; cvta.to.shared.u64 t, %1; cvt.u32.u64 %0, t; }" : "=r"(a) : "l"(p));
    return a;
}

#define LDM_X4(r, a) \
    asm volatile("ldmatrix.sync.aligned.m8n8.x4.shared.b16 {%0,%1,%2,%3}, [%4];" \
        : "=r"((r)[0]), "=r"((r)[1]), "=r"((r)[2]), "=r"((r)[3]) : "r"(a))
#define LDM_X2(r0, r1, a) \
    asm volatile("ldmatrix.sync.aligned.m8n8.x2.shared.b16 {%0,%1}, [%2];" \
        : "=r"(r0), "=r"(r1) : "r"(a))
#define MMA16816(c, a, b0v, b1v) \
    asm volatile("mma.sync.aligned.m16n8k16.row.col.f32.bf16.bf16.f32 " \
        "{%0,%1,%2,%3}, {%4,%5,%6,%7}, {%8,%9}, {%0,%1,%2,%3};" \
        : "+f"((c)[0]), "+f"((c)[1]), "+f"((c)[2]), "+f"((c)[3]) \
        : "r"((a)[0]), "r"((a)[1]), "r"((a)[2]), "r"((a)[3]), "r"(b0v), "r"(b1v))

// ---------------- phase: copy B image -> HMMA (3-term bf16 split) -> GBN+GLU epilogue ----------------
// MODE 0: GLU out (bf16 hi/lo) -> h1 images; MODE 1: sigmoid -> gmem out; MODE 2: att update in gmem
template<int K, int MODE>
__device__ void run_phase(char* smem, uint32_t sb, int ntiles,
                          const __nv_bfloat16* __restrict__ imgs,
                          const float* __restrict__ gam, const float* __restrict__ bet,
                          int pair0, uint32_t aoff,
                          int w, int lane, int t,
                          float* __restrict__ gatt_ch, float* __restrict__ outb)
{
    constexpr int IMGB = 64 * K * 2 * 2;       // bytes per tile image (hi+lo)
    constexpr int N16  = IMGB / 16;
    constexpr uint32_t ALO = 128 * K * 2;      // lo-image byte offset within A/H
    constexpr uint32_t BLO = 64 * K * 2;
    const float* sTau = (const float*)(smem + OFF_TAU);

    // --- per-lane constant addressing ---
    const int lrow = (lane & 7) + ((lane >> 3) & 1) * 8;   // A row within 16-tile
    const int kal  = (lane >> 4) * 8;                       // A k offset per lane half
    uint32_t arow[8];
#pragma unroll
    for (int tt = 0; tt < 8; tt++) {
        int row = 16 * tt + lrow;
        arow[tt] = sb + aoff + (uint32_t)((row >> 3) * 1024 + (row & 7) * 128);
    }
    const uint32_t axor = (uint32_t)((lrow & 7) << 4);
    const int bl8 = lane & 15;
    const int jf  = bl8 & 7;
    const int nB  = (jf < 4) ? (4 * w + jf) : (28 + 4 * w + jf);   // a-cols / gate-cols
    const int kbl = (bl8 >> 3) * 8;
    const uint32_t brow = sb + (uint32_t)OFF_B + (uint32_t)((nB >> 3) * 1024 + (nB & 7) * 128);
    const uint32_t bxor = (uint32_t)((nB & 7) << 4);

    for (int i = 0; i < ntiles; i++) {
        // ---- copy tile's B image (hi+lo) into SMEM ----
        {
            const uint4* s = (const uint4*)imgs + (size_t)i * N16;
            uint4* d = (uint4*)(smem + OFF_B);
            for (int ii = t; ii < N16; ii += 256) d[ii] = __ldg(s + ii);
        }
        __syncthreads();

        // ---- HMMA mainloop ----
        float acc[8][4];
#pragma unroll
        for (int tt = 0; tt < 8; tt++)
#pragma unroll
            for (int c = 0; c < 4; c++) acc[tt][c] = 0.0f;

#pragma unroll
        for (int ks = 0; ks < K / 16; ks++) {
            const int ka = ks * 16 + kal;
            const uint32_t kterm = (uint32_t)((ka >> 6) * 16384) + ((uint32_t)((ka & 63) * 2) ^ axor);
            const int kb = ks * 16 + kbl;
            const uint32_t bterm = (uint32_t)((kb >> 6) * 8192) + ((uint32_t)((kb & 63) * 2) ^ bxor);
            uint32_t bh0, bh1, bl0, bl1;
            LDM_X2(bh0, bh1, brow + bterm);
            LDM_X2(bl0, bl1, brow + BLO + bterm);
            uint32_t a[8][4];
#pragma unroll
            for (int tt = 0; tt < 8; tt++) LDM_X4(a[tt], arow[tt] + kterm);
#pragma unroll
            for (int tt = 0; tt < 8; tt++) MMA16816(acc[tt], a[tt], bh0, bh1);
#pragma unroll
            for (int tt = 0; tt < 8; tt++) MMA16816(acc[tt], a[tt], bl0, bl1);
#pragma unroll
            for (int tt = 0; tt < 8; tt++) LDM_X4(a[tt], arow[tt] + ALO + kterm);
#pragma unroll
            for (int tt = 0; tt < 8; tt++) MMA16816(acc[tt], a[tt], bh0, bh1);
        }

        // ---- epilogue: Ghost-BN + GLU (fully in-warp) ----
        const int lm = lane & 3;
        const bool isA = lm < 2;
        const int f0 = 2 * lm;
        const int pairB = pair0 + 32 * i;
        const int jb = pairB + 4 * w + (f0 & 3);    // a-column index (global pair id)

        float s0 = 0.f, s1 = 0.f, q0 = 0.f, q1 = 0.f;
#pragma unroll
        for (int tt = 0; tt < 8; tt++) {
            s0 += acc[tt][0] + acc[tt][2];
            s1 += acc[tt][1] + acc[tt][3];
            q0 += acc[tt][0] * acc[tt][0] + acc[tt][2] * acc[tt][2];
            q1 += acc[tt][1] * acc[tt][1] + acc[tt][3] * acc[tt][3];
        }
#pragma unroll
        for (int o = 4; o <= 16; o <<= 1) {
            s0 += __shfl_xor_sync(FULLM, s0, o);
            s1 += __shfl_xor_sync(FULLM, s1, o);
            q0 += __shfl_xor_sync(FULLM, q0, o);
            q1 += __shfl_xor_sync(FULLM, q1, o);
        }
        float mean0 = s0 * (1.f / 128.f), var0 = q0 * (1.f / 128.f) - mean0 * mean0;
        float mean1 = s1 * (1.f / 128.f), var1 = q1 * (1.f / 128.f) - mean1 * mean1;
        float rstd0 = rsqrtf(var0 + BN_EPS), rstd1 = rsqrtf(var1 + BN_EPS);
        const int jgb = jb + (isA ? 0 : 192);
        float ga0 = __ldg(gam + jgb) * rstd0,     bb0 = __ldg(bet + jgb) - mean0 * ga0;
        float ga1 = __ldg(gam + jgb + 1) * rstd1, bb1 = __ldg(bet + jgb + 1) - mean1 * ga1;

#pragma unroll
        for (int tt = 0; tt < 8; tt++) {
            const int row0 = 16 * tt + (lane >> 2);
            const int row1 = row0 + 8;
            float v0 = acc[tt][0] * ga0 + bb0;
            float v1 = acc[tt][1] * ga1 + bb1;
            float v2 = acc[tt][2] * ga0 + bb0;
            float v3 = acc[tt][3] * ga1 + bb1;
            float p0 = __shfl_xor_sync(FULLM, v0, 2);
            float p1 = __shfl_xor_sync(FULLM, v1, 2);
            float p2 = __shfl_xor_sync(FULLM, v2, 2);
            float p3 = __shfl_xor_sync(FULLM, v3, 2);
            float g0 = isA ? v0 * sigf(p0) : p0 * sigf(v0);
            float g1 = isA ? v1 * sigf(p1) : p1 * sigf(v1);
            float g2 = isA ? v2 * sigf(p2) : p2 * sigf(v2);
            float g3 = isA ? v3 * sigf(p3) : p3 * sigf(v3);

            if (MODE == 0) {
                uint32_t o0 = (uint32_t)(((row0 >> 3) + (jb >> 6) * 16) * 1024 + (row0 & 7) * 128)
                              + ((uint32_t)((jb & 63) * 2) ^ ((uint32_t)(row0 & 7) << 4));
                uint32_t o1 = (uint32_t)(((row1 >> 3) + (jb >> 6) * 16) * 1024 + (row1 & 7) * 128)
                              + ((uint32_t)((jb & 63) * 2) ^ ((uint32_t)(row1 & 7) << 4));
                __nv_bfloat16 h0 = __float2bfloat16(g0), h1 = __float2bfloat16(g1);
                __nv_bfloat16 h2 = __float2bfloat16(g2), h3 = __float2bfloat16(g3);
                if (isA) {
                    __nv_bfloat162 ph; ph.x = h0; ph.y = h1;
                    __nv_bfloat162 qh; qh.x = h2; qh.y = h3;
                    *(__nv_bfloat162*)(smem + OFF_H + o0) = ph;
                    *(__nv_bfloat162*)(smem + OFF_H + o1) = qh;
                } else {
                    __nv_bfloat162 pl, ql;
                    pl.x = __float2bfloat16(g0 - __bfloat162float(h0));
                    pl.y = __float2bfloat16(g1 - __bfloat162float(h1));
                    ql.x = __float2bfloat16(g2 - __bfloat162float(h2));
                    ql.y = __float2bfloat16(g3 - __bfloat162float(h3));
                    *(__nv_bfloat162*)(smem + OFF_H + 49152 + o0) = pl;
                    *(__nv_bfloat162*)(smem + OFF_H + 49152 + o1) = ql;
                }
            } else if (MODE == 1) {
                if (isA) {
                    *(float2*)(outb + (size_t)row0 * 64 + jb) = make_float2(sigf(g0), sigf(g1));
                    *(float2*)(outb + (size_t)row1 * 64 + jb) = make_float2(sigf(g2), sigf(g3));
                }
            } else {  // MODE 2: att update
                if (isA) {
                    const int ac = jb - 64;
                    float2* ap0 = (float2*)(gatt_ch + row0 * 128 + ac);
                    float2* ap1 = (float2*)(gatt_ch + row1 * 128 + ac);
                    float2 old0 = *ap0, old1 = *ap1;
                    float t0 = sTau[row0], t1 = sTau[row1];
                    float m0 = fmaxf(old0.x - t0, 0.f), m1 = fmaxf(old0.y - t0, 0.f);
                    float m2 = fmaxf(old1.x - t1, 0.f), m3 = fmaxf(old1.y - t1, 0.f);
                    *ap0 = make_float2(1.3f * sigf(g0) * (1.f - m0), 1.3f * sigf(g1) * (1.f - m1));
                    *ap1 = make_float2(1.3f * sigf(g2) * (1.f - m2), 1.3f * sigf(g3) * (1.f - m3));
                }
            }
        }
        __syncthreads();
    }
}

// ---------------- pre/post kernels ----------------
__global__ void k_zero() {
    int t = threadIdx.x;
    if (t < 128) { g_sum[t] = 0.0f; g_sumsq[t] = 0.0f; }
    if (t == 0) g_mloss = 0.0f;
}
__global__ void k_attinit() {
    size_t i = (size_t)blockIdx.x * 1024 + threadIdx.x;
    g_att[i] = 1.0f;
}
__global__ void k_stats(const float* __restrict__ x) {
    const int col = threadIdx.x;
    const int rb  = blockIdx.x * 128;
    float s = 0.0f, sq = 0.0f;
#pragma unroll 4
    for (int r = 0; r < 128; r++) {
        float v = x[(size_t)(rb + r) * 128 + col];
        s += v; sq = fmaf(v, v, sq);
    }
    atomicAdd(&g_sum[col], s);
    atomicAdd(&g_sumsq[col], sq);
}
__global__ void k_xn(const float* __restrict__ x,
                     const float* __restrict__ gam, const float* __restrict__ bet) {
    const int i4 = blockIdx.x * blockDim.x + threadIdx.x;
    const int c4 = (i4 & 31) << 2;
    float4 xv = ((const float4*)x)[i4];
    float o[4] = {xv.x, xv.y, xv.z, xv.w};
    const float inv = 1.0f / (float)BATCH;
#pragma unroll
    for (int j = 0; j < 4; j++) {
        const int c = c4 + j;
        float mean = g_sum[c] * inv;
        float var  = g_sumsq[c] * inv - mean * mean;
        o[j] = (o[j] - mean) * rsqrtf(var + BN_EPS) * gam[c] + bet[c];
    }
    ((float4*)g_xn)[i4] = make_float4(o[0], o[1], o[2], o[3]);
}

// Build B-tile SMEM images (hi & lo), blocked-atom SW128 swizzled. 54 blocks.
__global__ void k_wpack(const float* __restrict__ e0, const float* __restrict__ e1,
                        const float* __restrict__ d0, const float* __restrict__ d1) {
    int b = blockIdx.x;
    const float* W; int K, s, tile, base, pair0;
    if (b < 18)      { W = e0; K = 128; s = b / 6;      tile = b % 6;      base = WB_E0 + (s*6+tile)*16384; pair0 = 32*tile; }
    else if (b < 36) { W = d0; K = 128; s = (b-18)/6;   tile = (b-18)%6;   base = WB_D0 + (s*6+tile)*16384; pair0 = 32*tile; }
    else if (b < 48) { W = e1; K = 192; s = (b-36)/4;   tile = (b-36)%4;   base = WB_E1 + (s*4+tile)*24576; pair0 = 64+32*tile; }
    else             { W = d1; K = 192; s = (b-48)/2;   tile = (b-48)%2;   base = WB_D1 + (s*2+tile)*24576; pair0 = 32*tile; }
    const float* Ws = W + (size_t)s * 384 * K;
    __nv_bfloat16* img = g_wb + base;
    const int tot = 64 * K;
    for (int idx = threadIdx.x; idx < tot; idx += blockDim.x) {
        int n = idx / K, k = idx % K;
        int j = pair0 + (n < 32 ? n : n - 32 + 192);
        float v = __ldg(Ws + (size_t)j * K + k);
        __nv_bfloat16 hi = __float2bfloat16(v);
        __nv_bfloat16 lo = __float2bfloat16(v - __bfloat162float(hi));
        uint32_t bo = (uint32_t)(((n >> 3) + (k >> 6) * 8) * 1024 + (n & 7) * 128 + (k & 63) * 2);
        bo ^= (bo >> 3) & 0x70;
        img[bo >> 1] = hi;
        img[(size_t)tot + (bo >> 1)] = lo;
    }
}

__global__ void k_fin(float* __restrict__ outp) {
    outp[(size_t)NSTEPS * BATCH * 64] = g_mloss * (1.0f / ((float)BATCH * (float)NSTEPS));
}

// ---------------- main fused kernel: one CTA = one 128-row GBN chunk ----------------
__global__ void __launch_bounds__(256, 1) tabnet_main(
    const float* __restrict__ encg0, const float* __restrict__ encb0,
    const float* __restrict__ encg1, const float* __restrict__ encb1,
    const float* __restrict__ decg0, const float* __restrict__ decb0,
    const float* __restrict__ decg1, const float* __restrict__ decb1,
    float* __restrict__ outp)
{
    extern __shared__ char smem[];
    uint32_t sb = smem_to_u32(smem);
    const int t = threadIdx.x, lane = t & 31, w = t >> 5;
    const int chunk = blockIdx.x;
    float* gatt_ch = g_att + (size_t)chunk * 16384;
    const float* xnb = g_xn + (size_t)chunk * 16384;
    float* sTau = (float*)(smem + OFF_TAU);

    float mloss = 0.0f;

    for (int s = 0; s < NSTEPS; s++) {
        // ---- sparsemax (Michelot, exact) + mask + A image build (bf16 hi/lo) ----
        for (int rr = 0; rr < 16; rr++) {
            const int row = w * 16 + rr;
            float2 za = *(const float2*)(gatt_ch + row * 128 + 2 * lane);
            float2 zb = *(const float2*)(gatt_ch + row * 128 + 64 + 2 * lane);
            float z0 = za.x, z1 = za.y, z2 = zb.x, z3 = zb.y;
            float mx = wmax(fmaxf(fmaxf(z0, z1), fmaxf(z2, z3)));
            z0 -= mx; z1 -= mx; z2 -= mx; z3 -= mx;
            float tau = (wsum(z0 + z1 + z2 + z3) - 1.0f) * (1.0f / 128.0f);
            for (int it = 0; it < 32; it++) {
                float sp = 0.f, kp = 0.f;
                if (z0 > tau) { sp += z0; kp += 1.f; }
                if (z1 > tau) { sp += z1; kp += 1.f; }
                if (z2 > tau) { sp += z2; kp += 1.f; }
                if (z3 > tau) { sp += z3; kp += 1.f; }
                sp = wsum(sp); kp = wsum(kp);
                float tn = (sp - 1.0f) / kp;
                if (tn == tau) break;
                tau = tn;
            }
            if (lane == 0) sTau[row] = tau + mx;
            float m0 = fmaxf(z0 - tau, 0.f), m1 = fmaxf(z1 - tau, 0.f);
            float m2 = fmaxf(z2 - tau, 0.f), m3 = fmaxf(z3 - tau, 0.f);
            mloss += m0 * __logf(m0 + 1e-10f) + m1 * __logf(m1 + 1e-10f)
                   + m2 * __logf(m2 + 1e-10f) + m3 * __logf(m3 + 1e-10f);
            float2 xa = *(const float2*)(xnb + row * 128 + 2 * lane);
            float2 xb = *(const float2*)(xnb + row * 128 + 64 + 2 * lane);
            float v0 = m0 * xa.x, v1 = m1 * xa.y, v2 = m2 * xb.x, v3 = m3 * xb.y;
            uint32_t rb = (uint32_t)((row >> 3) * 1024 + (row & 7) * 128);
            uint32_t b0 = rb + 4 * lane;         b0 ^= (b0 >> 3) & 0x70;
            uint32_t b1 = rb + 16384 + 4 * lane; b1 ^= (b1 >> 3) & 0x70;
            __nv_bfloat16 h0 = __float2bfloat16(v0), h1 = __float2bfloat16(v1);
            __nv_bfloat16 h2 = __float2bfloat16(v2), h3 = __float2bfloat16(v3);
            __nv_bfloat162 p01; p01.x = h0; p01.y = h1;
            __nv_bfloat162 p23; p23.x = h2; p23.y = h3;
            *(__nv_bfloat162*)(smem + OFF_A + b0) = p01;
            *(__nv_bfloat162*)(smem + OFF_A + b1) = p23;
            __nv_bfloat162 l01, l23;
            l01.x = __float2bfloat16(v0 - __bfloat162float(h0));
            l01.y = __float2bfloat16(v1 - __bfloat162float(h1));
            l23.x = __float2bfloat16(v2 - __bfloat162float(h2));
            l23.y = __float2bfloat16(v3 - __bfloat162float(h3));
            *(__nv_bfloat162*)(smem + OFF_A + 32768 + b0) = l01;
            *(__nv_bfloat162*)(smem + OFF_A + 32768 + b1) = l23;
        }
        __syncthreads();

        if (s < NSTEPS - 1) {
            run_phase<128, 0>(smem, sb, 6, g_wb + WB_E0 + (size_t)s * 6 * 16384,
                              encg0, encb0, 0, OFF_A, w, lane, t, gatt_ch, nullptr);
            run_phase<192, 2>(smem, sb, 4, g_wb + WB_E1 + (size_t)s * 4 * 24576,
                              encg1, encb1, 64, OFF_H, w, lane, t, gatt_ch, nullptr);
        }
        run_phase<128, 0>(smem, sb, 6, g_wb + WB_D0 + (size_t)s * 6 * 16384,
                          decg0, decb0, 0, OFF_A, w, lane, t, gatt_ch, nullptr);
        run_phase<192, 1>(smem, sb, 2, g_wb + WB_D1 + (size_t)s * 2 * 24576,
                          decg1, decb1, 0, OFF_H, w, lane, t, gatt_ch,
                          outp + ((size_t)s * BATCH + (size_t)chunk * 128) * 64);
    }

    mloss = wsum(mloss);
    if (lane == 0) atomicAdd(&g_mloss, mloss);
}

// ---------------- launch ----------------
extern "C" void kernel_launch(void* const* d_in, const int* in_sizes, int n_in,
                              void* d_out, int out_size) {
    const float* x     = (const float*)d_in[0];
    const float* ig    = (const float*)d_in[1];
    const float* ib    = (const float*)d_in[2];
    const float* encW0 = (const float*)d_in[3];
    const float* encg0 = (const float*)d_in[4];
    const float* encb0 = (const float*)d_in[5];
    const float* encW1 = (const float*)d_in[6];
    const float* encg1 = (const float*)d_in[7];
    const float* encb1 = (const float*)d_in[8];
    const float* decW0 = (const float*)d_in[9];
    const float* decg0 = (const float*)d_in[10];
    const float* decb0 = (const float*)d_in[11];
    const float* decW1 = (const float*)d_in[12];
    const float* decg1 = (const float*)d_in[13];
    const float* decb1 = (const float*)d_in[14];
    float* out = (float*)d_out;

    cudaFuncSetAttribute(tabnet_main, cudaFuncAttributeMaxDynamicSharedMemorySize, SMEM_BYTES);

    k_zero<<<1, 128>>>();
    k_attinit<<<BATCH * 128 / 1024, 1024>>>();
    k_stats<<<BATCH / 128, 128>>>(x);
    k_xn<<<(BATCH * 128 / 4) / 256, 256>>>(x, ig, ib);
    k_wpack<<<54, 256>>>(encW0, encW1, decW0, decW1);
    tabnet_main<<<BATCH / 128, 256, SMEM_BYTES>>>(
        encg0, encb0, encg1, encb1,
        decg0, decb0, decg1, decb1, out);
    k_fin<<<1, 1>>>(out);
}

// round 10
// speedup vs baseline: 1.6410x; 1.6410x over previous
#include <cuda_runtime.h>
#include <cuda_bf16.h>
#include <cstdint>

#define BATCH   32768
#define NSTEPS  3
#define BN_EPS  1e-5f
#define FULLM   0xffffffffu

union F2U { unsigned long long u; float2 f; };

// ---------------- SMEM layout (byte offsets, 1024-aligned) ----------------
#define OFF_A     0        // masked_x bf16: hi 32768 + lo 32768
#define OFF_H     65536    // h1 bf16: hi 49152 + lo 49152
#define OFF_B     163840   // B tile image (hi+lo), up to 49152
#define OFF_TAU   212992   // 128 floats
#define OFF_STATS 213504   // float4[256] = 4096 B
#define OFF_CST   217600   // float2[64] = 512 B
#define SMEM_BYTES 218112

// ---------------- device scratch ----------------
__device__ float g_sum[128];
__device__ float g_sumsq[128];
__device__ float g_mloss;
__device__ float g_xn[(size_t)BATCH * 128];
__device__ float g_att[(size_t)BATCH * 128];
__device__ __align__(16) __nv_bfloat16 g_wb[1032192];   // pre-swizzled hi/lo weight images

#define WB_E0 0
#define WB_D0 294912
#define WB_E1 589824
#define WB_D1 884736

// ---------------- helpers ----------------
__device__ __forceinline__ float wsum(float v) {
#pragma unroll
    for (int o = 16; o > 0; o >>= 1) v += __shfl_xor_sync(FULLM, v, o);
    return v;
}
__device__ __forceinline__ float wmax(float v) {
#pragma unroll
    for (int o = 16; o > 0; o >>= 1) v = fmaxf(v, __shfl_xor_sync(FULLM, v, o));
    return v;
}
__device__ __forceinline__ float sigf(float x) { return 1.0f / (1.0f + __expf(-x)); }

__device__ __forceinline__ uint32_t smem_to_u32(const void* p) {
    uint32_t a;
    asm("{ .reg .u64 t; cvta.to.shared.u64 t, %1; cvt.u32.u64 %0, t; }" : "=r"(a) : "l"(p));
    return a;
}

#define LDM_X4(r, a) \
    asm volatile("ldmatrix.sync.aligned.m8n8.x4.shared.b16 {%0,%1,%2,%3}, [%4];" \
        : "=r"((r)[0]), "=r"((r)[1]), "=r"((r)[2]), "=r"((r)[3]) : "r"(a))
#define MMA16816(c, a, b0v, b1v) \
    asm volatile("mma.sync.aligned.m16n8k16.row.col.f32.bf16.bf16.f32 " \
        "{%0,%1,%2,%3}, {%4,%5,%6,%7}, {%8,%9}, {%0,%1,%2,%3};" \
        : "+f"((c)[0]), "+f"((c)[1]), "+f"((c)[2]), "+f"((c)[3]) \
        : "r"((a)[0]), "r"((a)[1]), "r"((a)[2]), "r"((a)[3]), "r"(b0v), "r"(b1v))

// ---------------- phase: prefetched B -> HMMA (3-term bf16 split) -> GBN+GLU epilogue ----------------
// Warp w owns rows 16w..16w+15, all 64 tile cols (32 a + 32 gate).
// MODE 0: GLU out (bf16 hi/lo) -> h1 images; MODE 1: sigmoid -> gmem out; MODE 2: att update in gmem
template<int K, int MODE>
__device__ void run_phase(char* smem, uint32_t sb, int ntiles,
                          const __nv_bfloat16* __restrict__ imgs,
                          const float* __restrict__ gam, const float* __restrict__ bet,
                          int pair0, uint32_t aoff, int first,
                          int w, int lane, int t,
                          float* __restrict__ gatt_ch, float* __restrict__ outb)
{
    constexpr int N16 = 16 * K;                // uint4 per tile image (hi+lo)
    constexpr int NPF = N16 / 256;
    constexpr uint32_t ALO = 128 * K * 2;      // lo-image byte offset within A/H
    constexpr uint32_t BLO = 64 * K * 2;
    const float*  sTau = (const float*)(smem + OFF_TAU);
    float4* sStats = (float4*)(smem + OFF_STATS);
    float2* sCst   = (float2*)(smem + OFF_CST);

    // ---- per-lane constant addressing ----
    const int lrow = (lane & 7) + ((lane >> 3) & 1) * 8;
    const int row16 = 16 * w + lrow;
    const uint32_t arow = sb + aoff + (uint32_t)((row16 >> 3) * 1024 + (row16 & 7) * 128);
    const uint32_t axor = (uint32_t)((row16 & 7) << 4);
    const int ka_off = (lane >> 4) * 8;

    const int bn = ((lane >> 4) << 3) + (lane & 7);        // 0..15
    const int bk = ((lane >> 3) & 1) * 8;
    const uint32_t bxor = (uint32_t)((bn & 7) << 4);
    uint32_t brow_g[4];
#pragma unroll
    for (int g = 0; g < 4; g++)
        brow_g[g] = sb + (uint32_t)OFF_B + (uint32_t)((2 * g + (bn >> 3)) * 1024 + (bn & 7) * 128);

    const uint4* wsrc = (const uint4*)imgs;
    uint4* bdst = (uint4*)(smem + OFF_B);

    // tile 0 B copy
    for (int ii = t; ii < N16; ii += 256) bdst[ii] = __ldg(wsrc + ii);
    __syncthreads();

#pragma unroll 1
    for (int i = 0; i < ntiles; i++) {
        // ---- prefetch next tile's B image into registers ----
        uint4 pf[NPF];
        if (i + 1 < ntiles) {
            const uint4* s = wsrc + (size_t)(i + 1) * N16;
#pragma unroll
            for (int n = 0; n < NPF; n++) pf[n] = __ldg(s + t + n * 256);
        }

        // ---- HMMA mainloop ----
        float acc[8][4];
#pragma unroll
        for (int tt = 0; tt < 8; tt++)
#pragma unroll
            for (int c = 0; c < 4; c++) acc[tt][c] = 0.0f;

#pragma unroll
        for (int ks = 0; ks < K / 16; ks++) {
            const int ka = ks * 16 + ka_off;
            const uint32_t aterm = (uint32_t)((ka >> 6) * 16384) + ((uint32_t)((ka & 63) * 2) ^ axor);
            const int kb = ks * 16 + bk;
            const uint32_t bterm = (uint32_t)((kb >> 6) * 8192) + ((uint32_t)((kb & 63) * 2) ^ bxor);
            uint32_t ah[4], al[4];
            LDM_X4(ah, arow + aterm);
            LDM_X4(al, arow + ALO + aterm);
            uint32_t bh[4][4], bl[4][4];
#pragma unroll
            for (int g = 0; g < 4; g++) {
                LDM_X4(bh[g], brow_g[g] + bterm);
                LDM_X4(bl[g], brow_g[g] + BLO + bterm);
            }
#pragma unroll
            for (int tt = 0; tt < 8; tt++) {
                const int g = tt >> 1, h2 = (tt & 1) * 2;
                MMA16816(acc[tt], ah, bh[g][h2], bh[g][h2 + 1]);
                MMA16816(acc[tt], ah, bl[g][h2], bl[g][h2 + 1]);
                MMA16816(acc[tt], al, bh[g][h2], bh[g][h2 + 1]);
            }
        }

        const int pairB = pair0 + 32 * i;

        // ---- Ghost-BN stats: in-warp reduce over 16 rows, combine across 8 warps ----
#pragma unroll
        for (int tt = 0; tt < 8; tt++) {
            F2U S, Q;
            S.f.x = acc[tt][0] + acc[tt][2];
            S.f.y = acc[tt][1] + acc[tt][3];
            Q.f.x = acc[tt][0] * acc[tt][0] + acc[tt][2] * acc[tt][2];
            Q.f.y = acc[tt][1] * acc[tt][1] + acc[tt][3] * acc[tt][3];
#pragma unroll
            for (int o = 4; o <= 16; o <<= 1) {
                unsigned long long ss = __shfl_xor_sync(FULLM, S.u, o);
                unsigned long long qq = __shfl_xor_sync(FULLM, Q.u, o);
                asm("add.rn.f32x2 %0, %0, %1;" : "+l"(S.u) : "l"(ss));
                asm("add.rn.f32x2 %0, %0, %1;" : "+l"(Q.u) : "l"(qq));
            }
            if ((lane >> 2) == 0)
                sStats[w * 32 + tt * 4 + lane] = make_float4(S.f.x, S.f.y, Q.f.x, Q.f.y);
        }
        __syncthreads();
        if (t < 64) {
            const int c = t;
            float s = 0.f, q = 0.f;
#pragma unroll
            for (int w8 = 0; w8 < 8; w8++) {
                float4 v = sStats[w8 * 32 + (c >> 1)];
                s += (c & 1) ? v.y : v.x;
                q += (c & 1) ? v.w : v.z;
            }
            float mean = s * (1.f / 128.f);
            float var  = q * (1.f / 128.f) - mean * mean;
            float rstd = rsqrtf(var + BN_EPS);
            const int j = (c < 32) ? (pairB + c) : (pairB + (c - 32) + 192);
            float ga = __ldg(gam + j) * rstd;
            sCst[c] = make_float2(ga, __ldg(bet + j) - mean * ga);
        }
        __syncthreads();

        // ---- apply: GLU (gate is register-local: tile t+4) + mode write ----
        const int c0 = 2 * (lane & 3);
        const int r0 = 16 * w + (lane >> 2), r1 = r0 + 8;
#pragma unroll
        for (int tt = 0; tt < 4; tt++) {
            const int ca = 8 * tt + c0;
            float2 k0 = sCst[ca], k1 = sCst[ca + 1];
            float2 q0 = sCst[ca + 32], q1 = sCst[ca + 33];
            float glu00 = (acc[tt][0] * k0.x + k0.y) * sigf(acc[tt + 4][0] * q0.x + q0.y);
            float glu01 = (acc[tt][1] * k1.x + k1.y) * sigf(acc[tt + 4][1] * q1.x + q1.y);
            float glu10 = (acc[tt][2] * k0.x + k0.y) * sigf(acc[tt + 4][2] * q0.x + q0.y);
            float glu11 = (acc[tt][3] * k1.x + k1.y) * sigf(acc[tt + 4][3] * q1.x + q1.y);
            const int jb = pairB + ca;

            if (MODE == 0) {
                const uint32_t jt = (uint32_t)((jb >> 6) * 16 * 1024) + ((uint32_t)((jb & 63) * 2));
                uint32_t o0 = ((r0 >> 3) * 1024 + (r0 & 7) * 128) + (jt ^ ((uint32_t)(r0 & 7) << 4));
                uint32_t o1 = ((r1 >> 3) * 1024 + (r1 & 7) * 128) + (jt ^ ((uint32_t)(r1 & 7) << 4));
                __nv_bfloat16 h00 = __float2bfloat16(glu00), h01 = __float2bfloat16(glu01);
                __nv_bfloat16 h10 = __float2bfloat16(glu10), h11 = __float2bfloat16(glu11);
                __nv_bfloat162 p0; p0.x = h00; p0.y = h01;
                __nv_bfloat162 p1; p1.x = h10; p1.y = h11;
                *(__nv_bfloat162*)(smem + OFF_H + o0) = p0;
                *(__nv_bfloat162*)(smem + OFF_H + o1) = p1;
                __nv_bfloat162 l0, l1;
                l0.x = __float2bfloat16(glu00 - __bfloat162float(h00));
                l0.y = __float2bfloat16(glu01 - __bfloat162float(h01));
                l1.x = __float2bfloat16(glu10 - __bfloat162float(h10));
                l1.y = __float2bfloat16(glu11 - __bfloat162float(h11));
                *(__nv_bfloat162*)(smem + OFF_H + 49152 + o0) = l0;
                *(__nv_bfloat162*)(smem + OFF_H + 49152 + o1) = l1;
            } else if (MODE == 1) {
                *(float2*)(outb + (size_t)r0 * 64 + jb) = make_float2(sigf(glu00), sigf(glu01));
                *(float2*)(outb + (size_t)r1 * 64 + jb) = make_float2(sigf(glu10), sigf(glu11));
            } else {  // MODE 2: att update
                const int ac = jb - 64;
                float2* ap0 = (float2*)(gatt_ch + r0 * 128 + ac);
                float2* ap1 = (float2*)(gatt_ch + r1 * 128 + ac);
                float2 o0 = first ? make_float2(1.f, 1.f) : *ap0;
                float2 o1 = first ? make_float2(1.f, 1.f) : *ap1;
                float t0 = sTau[r0], t1 = sTau[r1];
                *ap0 = make_float2(1.3f * sigf(glu00) * (1.f - fmaxf(o0.x - t0, 0.f)),
                                   1.3f * sigf(glu01) * (1.f - fmaxf(o0.y - t0, 0.f)));
                *ap1 = make_float2(1.3f * sigf(glu10) * (1.f - fmaxf(o1.x - t1, 0.f)),
                                   1.3f * sigf(glu11) * (1.f - fmaxf(o1.y - t1, 0.f)));
            }
        }

        // ---- commit prefetched B ----
        if (i + 1 < ntiles) {
#pragma unroll
            for (int n = 0; n < NPF; n++) bdst[t + n * 256] = pf[n];
        }
        __syncthreads();
    }
}

// ---------------- pre/post kernels ----------------
__global__ void k_zero() {
    int t = threadIdx.x;
    if (t < 128) { g_sum[t] = 0.0f; g_sumsq[t] = 0.0f; }
    if (t == 0) g_mloss = 0.0f;
}
__global__ void k_stats(const float* __restrict__ x) {
    const int col = threadIdx.x;
    const int rb  = blockIdx.x * 128;
    float s = 0.0f, sq = 0.0f;
#pragma unroll 4
    for (int r = 0; r < 128; r++) {
        float v = x[(size_t)(rb + r) * 128 + col];
        s += v; sq = fmaf(v, v, sq);
    }
    atomicAdd(&g_sum[col], s);
    atomicAdd(&g_sumsq[col], sq);
}
__global__ void k_xn(const float* __restrict__ x,
                     const float* __restrict__ gam, const float* __restrict__ bet) {
    const int i4 = blockIdx.x * blockDim.x + threadIdx.x;
    const int c4 = (i4 & 31) << 2;
    float4 xv = ((const float4*)x)[i4];
    float o[4] = {xv.x, xv.y, xv.z, xv.w};
    const float inv = 1.0f / (float)BATCH;
#pragma unroll
    for (int j = 0; j < 4; j++) {
        const int c = c4 + j;
        float mean = g_sum[c] * inv;
        float var  = g_sumsq[c] * inv - mean * mean;
        o[j] = (o[j] - mean) * rsqrtf(var + BN_EPS) * gam[c] + bet[c];
    }
    ((float4*)g_xn)[i4] = make_float4(o[0], o[1], o[2], o[3]);
}

// Build B-tile SMEM images (hi & lo), blocked-atom SW128 swizzled. 54 blocks.
__global__ void k_wpack(const float* __restrict__ e0, const float* __restrict__ e1,
                        const float* __restrict__ d0, const float* __restrict__ d1) {
    int b = blockIdx.x;
    const float* W; int K, s, tile, base, pair0;
    if (b < 18)      { W = e0; K = 128; s = b / 6;      tile = b % 6;      base = WB_E0 + (s*6+tile)*16384; pair0 = 32*tile; }
    else if (b < 36) { W = d0; K = 128; s = (b-18)/6;   tile = (b-18)%6;   base = WB_D0 + (s*6+tile)*16384; pair0 = 32*tile; }
    else if (b < 48) { W = e1; K = 192; s = (b-36)/4;   tile = (b-36)%4;   base = WB_E1 + (s*4+tile)*24576; pair0 = 64+32*tile; }
    else             { W = d1; K = 192; s = (b-48)/2;   tile = (b-48)%2;   base = WB_D1 + (s*2+tile)*24576; pair0 = 32*tile; }
    const float* Ws = W + (size_t)s * 384 * K;
    __nv_bfloat16* img = g_wb + base;
    const int tot = 64 * K;
    for (int idx = threadIdx.x; idx < tot; idx += blockDim.x) {
        int n = idx / K, k = idx % K;
        int j = pair0 + (n < 32 ? n : n - 32 + 192);
        float v = __ldg(Ws + (size_t)j * K + k);
        __nv_bfloat16 hi = __float2bfloat16(v);
        __nv_bfloat16 lo = __float2bfloat16(v - __bfloat162float(hi));
        uint32_t bo = (uint32_t)(((n >> 3) + (k >> 6) * 8) * 1024 + (n & 7) * 128 + (k & 63) * 2);
        bo ^= (bo >> 3) & 0x70;
        img[bo >> 1] = hi;
        img[(size_t)tot + (bo >> 1)] = lo;
    }
}

__global__ void k_fin(float* __restrict__ outp) {
    outp[(size_t)NSTEPS * BATCH * 64] = g_mloss * (1.0f / ((float)BATCH * (float)NSTEPS));
}

// ---------------- main fused kernel: one CTA = one 128-row GBN chunk ----------------
__global__ void __launch_bounds__(256, 1) tabnet_main(
    const float* __restrict__ encg0, const float* __restrict__ encb0,
    const float* __restrict__ encg1, const float* __restrict__ encb1,
    const float* __restrict__ decg0, const float* __restrict__ decb0,
    const float* __restrict__ decg1, const float* __restrict__ decb1,
    float* __restrict__ outp)
{
    extern __shared__ char smem[];
    uint32_t sb = smem_to_u32(smem);
    const int t = threadIdx.x, lane = t & 31, w = t >> 5;
    const int chunk = blockIdx.x;
    float* gatt_ch = g_att + (size_t)chunk * 16384;
    const float* xnb = g_xn + (size_t)chunk * 16384;
    float* sTau = (float*)(smem + OFF_TAU);

    float mloss = 0.0f;

    for (int s = 0; s < NSTEPS; s++) {
        // ---- sparsemax (Michelot, exact) + mask + A image build (bf16 hi/lo) ----
        for (int rr = 0; rr < 16; rr++) {
            const int row = w * 16 + rr;
            float z0, z1, z2, z3;
            if (s == 0) { z0 = z1 = z2 = z3 = 1.0f; }
            else {
                float2 za = *(const float2*)(gatt_ch + row * 128 + 2 * lane);
                float2 zb = *(const float2*)(gatt_ch + row * 128 + 64 + 2 * lane);
                z0 = za.x; z1 = za.y; z2 = zb.x; z3 = zb.y;
            }
            float mx = wmax(fmaxf(fmaxf(z0, z1), fmaxf(z2, z3)));
            z0 -= mx; z1 -= mx; z2 -= mx; z3 -= mx;
            float tau = (wsum(z0 + z1 + z2 + z3) - 1.0f) * (1.0f / 128.0f);
            for (int it = 0; it < 32; it++) {
                float sp = 0.f, kp = 0.f;
                if (z0 > tau) { sp += z0; kp += 1.f; }
                if (z1 > tau) { sp += z1; kp += 1.f; }
                if (z2 > tau) { sp += z2; kp += 1.f; }
                if (z3 > tau) { sp += z3; kp += 1.f; }
                sp = wsum(sp); kp = wsum(kp);
                float tn = (sp - 1.0f) / kp;
                if (tn == tau) break;
                tau = tn;
            }
            if (lane == 0) sTau[row] = tau + mx;
            float m0 = fmaxf(z0 - tau, 0.f), m1 = fmaxf(z1 - tau, 0.f);
            float m2 = fmaxf(z2 - tau, 0.f), m3 = fmaxf(z3 - tau, 0.f);
            mloss += m0 * __logf(m0 + 1e-10f) + m1 * __logf(m1 + 1e-10f)
                   + m2 * __logf(m2 + 1e-10f) + m3 * __logf(m3 + 1e-10f);
            float2 xa = *(const float2*)(xnb + row * 128 + 2 * lane);
            float2 xb = *(const float2*)(xnb + row * 128 + 64 + 2 * lane);
            float v0 = m0 * xa.x, v1 = m1 * xa.y, v2 = m2 * xb.x, v3 = m3 * xb.y;
            uint32_t rb = (uint32_t)((row >> 3) * 1024 + (row & 7) * 128);
            uint32_t b0 = rb + 4 * lane;         b0 ^= (b0 >> 3) & 0x70;
            uint32_t b1 = rb + 16384 + 4 * lane; b1 ^= (b1 >> 3) & 0x70;
            __nv_bfloat16 h0 = __float2bfloat16(v0), h1 = __float2bfloat16(v1);
            __nv_bfloat16 h2 = __float2bfloat16(v2), h3 = __float2bfloat16(v3);
            __nv_bfloat162 p01; p01.x = h0; p01.y = h1;
            __nv_bfloat162 p23; p23.x = h2; p23.y = h3;
            *(__nv_bfloat162*)(smem + OFF_A + b0) = p01;
            *(__nv_bfloat162*)(smem + OFF_A + b1) = p23;
            __nv_bfloat162 l01, l23;
            l01.x = __float2bfloat16(v0 - __bfloat162float(h0));
            l01.y = __float2bfloat16(v1 - __bfloat162float(h1));
            l23.x = __float2bfloat16(v2 - __bfloat162float(h2));
            l23.y = __float2bfloat16(v3 - __bfloat162float(h3));
            *(__nv_bfloat162*)(smem + OFF_A + 32768 + b0) = l01;
            *(__nv_bfloat162*)(smem + OFF_A + 32768 + b1) = l23;
        }
        __syncthreads();

        if (s < NSTEPS - 1) {
            run_phase<128, 0>(smem, sb, 6, g_wb + WB_E0 + (size_t)s * 6 * 16384,
                              encg0, encb0, 0, OFF_A, 0, w, lane, t, gatt_ch, nullptr);
            run_phase<192, 2>(smem, sb, 4, g_wb + WB_E1 + (size_t)s * 4 * 24576,
                              encg1, encb1, 64, OFF_H, s == 0, w, lane, t, gatt_ch, nullptr);
        }
        run_phase<128, 0>(smem, sb, 6, g_wb + WB_D0 + (size_t)s * 6 * 16384,
                          decg0, decb0, 0, OFF_A, 0, w, lane, t, gatt_ch, nullptr);
        run_phase<192, 1>(smem, sb, 2, g_wb + WB_D1 + (size_t)s * 2 * 24576,
                          decg1, decb1, 0, OFF_H, 0, w, lane, t, gatt_ch,
                          outp + ((size_t)s * BATCH + (size_t)chunk * 128) * 64);
    }

    mloss = wsum(mloss);
    if (lane == 0) atomicAdd(&g_mloss, mloss);
}

// ---------------- launch ----------------
extern "C" void kernel_launch(void* const* d_in, const int* in_sizes, int n_in,
                              void* d_out, int out_size) {
    const float* x     = (const float*)d_in[0];
    const float* ig    = (const float*)d_in[1];
    const float* ib    = (const float*)d_in[2];
    const float* encW0 = (const float*)d_in[3];
    const float* encg0 = (const float*)d_in[4];
    const float* encb0 = (const float*)d_in[5];
    const float* encW1 = (const float*)d_in[6];
    const float* encg1 = (const float*)d_in[7];
    const float* encb1 = (const float*)d_in[8];
    const float* decW0 = (const float*)d_in[9];
    const float* decg0 = (const float*)d_in[10];
    const float* decb0 = (const float*)d_in[11];
    const float* decW1 = (const float*)d_in[12];
    const float* decg1 = (const float*)d_in[13];
    const float* decb1 = (const float*)d_in[14];
    float* out = (float*)d_out;

    cudaFuncSetAttribute(tabnet_main, cudaFuncAttributeMaxDynamicSharedMemorySize, SMEM_BYTES);

    k_zero<<<1, 128>>>();
    k_stats<<<BATCH / 128, 128>>>(x);
    k_xn<<<(BATCH * 128 / 4) / 256, 256>>>(x, ig, ib);
    k_wpack<<<54, 256>>>(encW0, encW1, decW0, decW1);
    tabnet_main<<<BATCH / 128, 256, SMEM_BYTES>>>(
        encg0, encb0, encg1, encb1,
        decg0, decb0, decg1, decb1, out);
    k_fin<<<1, 1>>>(out);
}

// round 13
// speedup vs baseline: 1.7733x; 1.0806x over previous
#include <cuda_runtime.h>
#include <cuda_bf16.h>
#include <cstdint>

#define BATCH   32768
#define NSTEPS  3
#define BN_EPS  1e-5f
#define FULLM   0xffffffffu

union F2U { unsigned long long u; float2 f; };

// ---------------- SMEM layout (byte offsets, 1024-aligned) ----------------
#define OFF_A     0        // masked_x bf16: hi 32768 + lo 32768
#define OFF_H     65536    // h1 bf16: hi 49152 + lo 49152
#define OFF_B     163840   // B tile image (hi+lo), up to 49152
#define OFF_TAU   212992   // 128 floats
#define OFF_STATS 213504   // float4[256] = 4096 B
#define OFF_CST   217600   // float2[64] = 512 B
#define SMEM_BYTES 218112

// ---------------- device scratch ----------------
__device__ float g_sum[128];
__device__ float g_sumsq[128];
__device__ float g_mloss;
__device__ float g_xn[(size_t)BATCH * 128];
__device__ float g_att[(size_t)BATCH * 128];
__device__ __align__(16) __nv_bfloat16 g_wb[1032192];   // pre-swizzled hi/lo weight images

#define WB_E0 0
#define WB_D0 294912
#define WB_E1 589824
#define WB_D1 884736

// ---------------- helpers ----------------
__device__ __forceinline__ float wsum(float v) {
#pragma unroll
    for (int o = 16; o > 0; o >>= 1) v += __shfl_xor_sync(FULLM, v, o);
    return v;
}
__device__ __forceinline__ float wmax(float v) {
#pragma unroll
    for (int o = 16; o > 0; o >>= 1) v = fmaxf(v, __shfl_xor_sync(FULLM, v, o));
    return v;
}
__device__ __forceinline__ float sigf(float x) { return 1.0f / (1.0f + __expf(-x)); }

__device__ __forceinline__ uint32_t smem_to_u32(const void* p) {
    uint32_t a;
    asm("{ .reg .u64 t; cvta.to.shared.u64 t, %1; cvt.u32.u64 %0, t; }" : "=r"(a) : "l"(p));
    return a;
}

#define LDM_X4(r, a) \
    asm volatile("ldmatrix.sync.aligned.m8n8.x4.shared.b16 {%0,%1,%2,%3}, [%4];" \
        : "=r"((r)[0]), "=r"((r)[1]), "=r"((r)[2]), "=r"((r)[3]) : "r"(a))
#define MMA16816(c, a, b0v, b1v) \
    asm volatile("mma.sync.aligned.m16n8k16.row.col.f32.bf16.bf16.f32 " \
        "{%0,%1,%2,%3}, {%4,%5,%6,%7}, {%8,%9}, {%0,%1,%2,%3};" \
        : "+f"((c)[0]), "+f"((c)[1]), "+f"((c)[2]), "+f"((c)[3]) \
        : "r"((a)[0]), "r"((a)[1]), "r"((a)[2]), "r"((a)[3]), "r"(b0v), "r"(b1v))

// ---------------- phase: prefetched B -> HMMA (3-term bf16 split) -> GBN+GLU epilogue ----------------
// 16 warps: rw = w&7 owns rows 16rw..16rw+15; h = w>>3 owns a-cols [16h,16h+16) + gates [32+16h,...).
// MODE 0: GLU out (bf16 hi/lo) -> h1 images; MODE 1: sigmoid -> gmem out; MODE 2: att update in gmem
template<int K, int MODE>
__device__ void run_phase(char* smem, uint32_t sb, int ntiles,
                          const __nv_bfloat16* __restrict__ imgs,
                          const float* __restrict__ gam, const float* __restrict__ bet,
                          int pair0, uint32_t aoff, int first,
                          int w, int lane, int t,
                          float* __restrict__ gatt_ch, float* __restrict__ outb)
{
    constexpr int N16 = 16 * K;                // uint4 per tile image (hi+lo)
    constexpr int NPF = N16 / 512;
    constexpr uint32_t ALO = 128 * K * 2;      // lo-image byte offset within A/H
    constexpr uint32_t BLO = 64 * K * 2;
    const float*  sTau = (const float*)(smem + OFF_TAU);
    float4* sStats = (float4*)(smem + OFF_STATS);
    float2* sCst   = (float2*)(smem + OFF_CST);

    const int rw = w & 7, h = w >> 3;

    // ---- A addressing ----
    const int lrow = (lane & 7) + ((lane >> 3) & 1) * 8;
    const int row16 = 16 * rw + lrow;
    const uint32_t arow = sb + aoff + (uint32_t)((row16 >> 3) * 1024 + (row16 & 7) * 128);
    const uint32_t axor = (uint32_t)((row16 & 7) << 4);
    const int ka_off = (lane >> 4) * 8;

    // ---- B addressing: two n16 groups (a-cols & gates) ----
    const int bsub = ((lane >> 4) << 3) + (lane & 7);      // 0..15
    const int bk   = ((lane >> 3) & 1) * 8;
    const int nA = 16 * h + bsub;
    const int nG = 32 + 16 * h + bsub;
    const uint32_t browA = sb + (uint32_t)OFF_B + (uint32_t)((nA >> 3) * 1024 + (nA & 7) * 128);
    const uint32_t browG = sb + (uint32_t)OFF_B + (uint32_t)((nG >> 3) * 1024 + (nG & 7) * 128);
    const uint32_t bxor = (uint32_t)((nA & 7) << 4);       // nG&7 == nA&7

    const uint4* wsrc = (const uint4*)imgs;
    uint4* bdst = (uint4*)(smem + OFF_B);

    // tile 0 B copy
    for (int ii = t; ii < N16; ii += 512) bdst[ii] = __ldg(wsrc + ii);
    __syncthreads();

#pragma unroll 1
    for (int i = 0; i < ntiles; i++) {
        // ---- prefetch next tile's B image into registers ----
        uint4 pf[NPF];
        if (i + 1 < ntiles) {
            const uint4* s = wsrc + (size_t)(i + 1) * N16;
#pragma unroll
            for (int n = 0; n < NPF; n++) pf[n] = __ldg(s + t + n * 512);
        }

        // ---- HMMA mainloop: acc[0..1] = a-col n8 groups, acc[2..3] = gate groups ----
        float acc[4][4];
#pragma unroll
        for (int g = 0; g < 4; g++)
#pragma unroll
            for (int c = 0; c < 4; c++) acc[g][c] = 0.0f;

#pragma unroll
        for (int ks = 0; ks < K / 16; ks++) {
            const int ka = ks * 16 + ka_off;
            const uint32_t aterm = (uint32_t)((ka >> 6) * 16384) + ((uint32_t)((ka & 63) * 2) ^ axor);
            const int kb = ks * 16 + bk;
            const uint32_t bterm = (uint32_t)((kb >> 6) * 8192) + ((uint32_t)((kb & 63) * 2) ^ bxor);
            uint32_t ah[4], al[4], bha[4], bla[4], bhg[4], blg[4];
            LDM_X4(ah, arow + aterm);
            LDM_X4(al, arow + ALO + aterm);
            LDM_X4(bha, browA + bterm);
            LDM_X4(bla, browA + BLO + bterm);
            LDM_X4(bhg, browG + bterm);
            LDM_X4(blg, browG + BLO + bterm);
#pragma unroll
            for (int g = 0; g < 2; g++) {
                MMA16816(acc[g], ah, bha[2 * g], bha[2 * g + 1]);
                MMA16816(acc[g], ah, bla[2 * g], bla[2 * g + 1]);
                MMA16816(acc[g], al, bha[2 * g], bha[2 * g + 1]);
                MMA16816(acc[2 + g], ah, bhg[2 * g], bhg[2 * g + 1]);
                MMA16816(acc[2 + g], ah, blg[2 * g], blg[2 * g + 1]);
                MMA16816(acc[2 + g], al, bhg[2 * g], bhg[2 * g + 1]);
            }
        }

        const int pairB = pair0 + 32 * i;

        // ---- Ghost-BN stats: butterfly over 16 rows, combine across 8 row-warps ----
#pragma unroll
        for (int g = 0; g < 4; g++) {
            F2U S, Q;
            S.f.x = acc[g][0] + acc[g][2];
            S.f.y = acc[g][1] + acc[g][3];
            Q.f.x = acc[g][0] * acc[g][0] + acc[g][2] * acc[g][2];
            Q.f.y = acc[g][1] * acc[g][1] + acc[g][3] * acc[g][3];
#pragma unroll
            for (int o = 4; o <= 16; o <<= 1) {
                unsigned long long ss = __shfl_xor_sync(FULLM, S.u, o);
                unsigned long long qq = __shfl_xor_sync(FULLM, Q.u, o);
                asm("add.rn.f32x2 %0, %0, %1;" : "+l"(S.u) : "l"(ss));
                asm("add.rn.f32x2 %0, %0, %1;" : "+l"(Q.u) : "l"(qq));
            }
            if ((lane >> 2) == 0) {
                const int cbase = (g < 2) ? (16 * h + 8 * g) : (32 + 16 * h + 8 * (g - 2));
                const int pairid = (cbase >> 1) + (lane & 3);
                sStats[pairid * 8 + rw] = make_float4(S.f.x, S.f.y, Q.f.x, Q.f.y);
            }
        }
        __syncthreads();
        if (t < 64) {
            const int c = t;
            float s = 0.f, q = 0.f;
#pragma unroll
            for (int r8 = 0; r8 < 8; r8++) {
                float4 v = sStats[(c >> 1) * 8 + r8];
                s += (c & 1) ? v.y : v.x;
                q += (c & 1) ? v.w : v.z;
            }
            float mean = s * (1.f / 128.f);
            float var  = q * (1.f / 128.f) - mean * mean;
            float rstd = rsqrtf(var + BN_EPS);
            const int j = (c < 32) ? (pairB + c) : (pairB + (c - 32) + 192);
            float ga = __ldg(gam + j) * rstd;
            sCst[c] = make_float2(ga, __ldg(bet + j) - mean * ga);
        }
        __syncthreads();

        // ---- apply: GLU (gate group is register-local: acc[2+g]) + mode write ----
        const int c0 = 2 * (lane & 3);
        const int r0 = 16 * rw + (lane >> 2), r1 = r0 + 8;
#pragma unroll
        for (int g = 0; g < 2; g++) {
            const int ca = 16 * h + 8 * g + c0;
            float2 k0 = sCst[ca], k1 = sCst[ca + 1];
            float2 q0 = sCst[ca + 32], q1 = sCst[ca + 33];
            float glu00 = (acc[g][0] * k0.x + k0.y) * sigf(acc[2 + g][0] * q0.x + q0.y);
            float glu01 = (acc[g][1] * k1.x + k1.y) * sigf(acc[2 + g][1] * q1.x + q1.y);
            float glu10 = (acc[g][2] * k0.x + k0.y) * sigf(acc[2 + g][2] * q0.x + q0.y);
            float glu11 = (acc[g][3] * k1.x + k1.y) * sigf(acc[2 + g][3] * q1.x + q1.y);
            const int jb = pairB + ca;

            if (MODE == 0) {
                const uint32_t jt = (uint32_t)((jb >> 6) * 16 * 1024) + ((uint32_t)((jb & 63) * 2));
                uint32_t o0 = ((r0 >> 3) * 1024 + (r0 & 7) * 128) + (jt ^ ((uint32_t)(r0 & 7) << 4));
                uint32_t o1 = ((r1 >> 3) * 1024 + (r1 & 7) * 128) + (jt ^ ((uint32_t)(r1 & 7) << 4));
                __nv_bfloat16 h00 = __float2bfloat16(glu00), h01 = __float2bfloat16(glu01);
                __nv_bfloat16 h10 = __float2bfloat16(glu10), h11 = __float2bfloat16(glu11);
                __nv_bfloat162 p0; p0.x = h00; p0.y = h01;
                __nv_bfloat162 p1; p1.x = h10; p1.y = h11;
                *(__nv_bfloat162*)(smem + OFF_H + o0) = p0;
                *(__nv_bfloat162*)(smem + OFF_H + o1) = p1;
                __nv_bfloat162 l0, l1;
                l0.x = __float2bfloat16(glu00 - __bfloat162float(h00));
                l0.y = __float2bfloat16(glu01 - __bfloat162float(h01));
                l1.x = __float2bfloat16(glu10 - __bfloat162float(h10));
                l1.y = __float2bfloat16(glu11 - __bfloat162float(h11));
                *(__nv_bfloat162*)(smem + OFF_H + 49152 + o0) = l0;
                *(__nv_bfloat162*)(smem + OFF_H + 49152 + o1) = l1;
            } else if (MODE == 1) {
                *(float2*)(outb + (size_t)r0 * 64 + jb) = make_float2(sigf(glu00), sigf(glu01));
                *(float2*)(outb + (size_t)r1 * 64 + jb) = make_float2(sigf(glu10), sigf(glu11));
            } else {  // MODE 2: att update
                const int ac = jb - 64;
                float2* ap0 = (float2*)(gatt_ch + r0 * 128 + ac);
                float2* ap1 = (float2*)(gatt_ch + r1 * 128 + ac);
                float2 o0 = first ? make_float2(1.f, 1.f) : *ap0;
                float2 o1 = first ? make_float2(1.f, 1.f) : *ap1;
                float t0 = sTau[r0], t1 = sTau[r1];
                *ap0 = make_float2(1.3f * sigf(glu00) * (1.f - fmaxf(o0.x - t0, 0.f)),
                                   1.3f * sigf(glu01) * (1.f - fmaxf(o0.y - t0, 0.f)));
                *ap1 = make_float2(1.3f * sigf(glu10) * (1.f - fmaxf(o1.x - t1, 0.f)),
                                   1.3f * sigf(glu11) * (1.f - fmaxf(o1.y - t1, 0.f)));
            }
        }

        // ---- commit prefetched B ----
        if (i + 1 < ntiles) {
#pragma unroll
            for (int n = 0; n < NPF; n++) bdst[t + n * 512] = pf[n];
        }
        __syncthreads();
    }
}

// ---------------- pre/post kernels ----------------
__global__ void k_zero() {
    int t = threadIdx.x;
    if (t < 128) { g_sum[t] = 0.0f; g_sumsq[t] = 0.0f; }
    if (t == 0) g_mloss = 0.0f;
}
__global__ void k_stats(const float* __restrict__ x) {
    const int col = threadIdx.x;
    const int rb  = blockIdx.x * 128;
    float s = 0.0f, sq = 0.0f;
#pragma unroll 4
    for (int r = 0; r < 128; r++) {
        float v = x[(size_t)(rb + r) * 128 + col];
        s += v; sq = fmaf(v, v, sq);
    }
    atomicAdd(&g_sum[col], s);
    atomicAdd(&g_sumsq[col], sq);
}
__global__ void k_xn(const float* __restrict__ x,
                     const float* __restrict__ gam, const float* __restrict__ bet) {
    const int i4 = blockIdx.x * blockDim.x + threadIdx.x;
    const int c4 = (i4 & 31) << 2;
    float4 xv = ((const float4*)x)[i4];
    float o[4] = {xv.x, xv.y, xv.z, xv.w};
    const float inv = 1.0f / (float)BATCH;
#pragma unroll
    for (int j = 0; j < 4; j++) {
        const int c = c4 + j;
        float mean = g_sum[c] * inv;
        float var  = g_sumsq[c] * inv - mean * mean;
        o[j] = (o[j] - mean) * rsqrtf(var + BN_EPS) * gam[c] + bet[c];
    }
    ((float4*)g_xn)[i4] = make_float4(o[0], o[1], o[2], o[3]);
}

// Build B-tile SMEM images (hi & lo), blocked-atom SW128 swizzled. 54 blocks.
__global__ void k_wpack(const float* __restrict__ e0, const float* __restrict__ e1,
                        const float* __restrict__ d0, const float* __restrict__ d1) {
    int b = blockIdx.x;
    const float* W; int K, s, tile, base, pair0;
    if (b < 18)      { W = e0; K = 128; s = b / 6;      tile = b % 6;      base = WB_E0 + (s*6+tile)*16384; pair0 = 32*tile; }
    else if (b < 36) { W = d0; K = 128; s = (b-18)/6;   tile = (b-18)%6;   base = WB_D0 + (s*6+tile)*16384; pair0 = 32*tile; }
    else if (b < 48) { W = e1; K = 192; s = (b-36)/4;   tile = (b-36)%4;   base = WB_E1 + (s*4+tile)*24576; pair0 = 64+32*tile; }
    else             { W = d1; K = 192; s = (b-48)/2;   tile = (b-48)%2;   base = WB_D1 + (s*2+tile)*24576; pair0 = 32*tile; }
    const float* Ws = W + (size_t)s * 384 * K;
    __nv_bfloat16* img = g_wb + base;
    const int tot = 64 * K;
    for (int idx = threadIdx.x; idx < tot; idx += blockDim.x) {
        int n = idx / K, k = idx % K;
        int j = pair0 + (n < 32 ? n : n - 32 + 192);
        float v = __ldg(Ws + (size_t)j * K + k);
        __nv_bfloat16 hi = __float2bfloat16(v);
        __nv_bfloat16 lo = __float2bfloat16(v - __bfloat162float(hi));
        uint32_t bo = (uint32_t)(((n >> 3) + (k >> 6) * 8) * 1024 + (n & 7) * 128 + (k & 63) * 2);
        bo ^= (bo >> 3) & 0x70;
        img[bo >> 1] = hi;
        img[(size_t)tot + (bo >> 1)] = lo;
    }
}

__global__ void k_fin(float* __restrict__ outp) {
    outp[(size_t)NSTEPS * BATCH * 64] = g_mloss * (1.0f / ((float)BATCH * (float)NSTEPS));
}

// ---------------- main fused kernel: one CTA = one 128-row GBN chunk ----------------
__global__ void __launch_bounds__(512, 1) tabnet_main(
    const float* __restrict__ encg0, const float* __restrict__ encb0,
    const float* __restrict__ encg1, const float* __restrict__ encb1,
    const float* __restrict__ decg0, const float* __restrict__ decb0,
    const float* __restrict__ decg1, const float* __restrict__ decb1,
    float* __restrict__ outp)
{
    extern __shared__ char smem[];
    uint32_t sb = smem_to_u32(smem);
    const int t = threadIdx.x, lane = t & 31, w = t >> 5;
    const int chunk = blockIdx.x;
    float* gatt_ch = g_att + (size_t)chunk * 16384;
    const float* xnb = g_xn + (size_t)chunk * 16384;
    float* sTau = (float*)(smem + OFF_TAU);

    float mloss = 0.0f;

    for (int s = 0; s < NSTEPS; s++) {
        // ---- sparsemax (Michelot, exact) + mask + A image build (bf16 hi/lo) ----
        for (int rr = 0; rr < 8; rr++) {
            const int row = w * 8 + rr;
            float z0, z1, z2, z3;
            if (s == 0) { z0 = z1 = z2 = z3 = 1.0f; }
            else {
                float2 za = *(const float2*)(gatt_ch + row * 128 + 2 * lane);
                float2 zb = *(const float2*)(gatt_ch + row * 128 + 64 + 2 * lane);
                z0 = za.x; z1 = za.y; z2 = zb.x; z3 = zb.y;
            }
            float mx = wmax(fmaxf(fmaxf(z0, z1), fmaxf(z2, z3)));
            z0 -= mx; z1 -= mx; z2 -= mx; z3 -= mx;
            float tau = (wsum(z0 + z1 + z2 + z3) - 1.0f) * (1.0f / 128.0f);
            for (int it = 0; it < 32; it++) {
                float sp = 0.f, kp = 0.f;
                if (z0 > tau) { sp += z0; kp += 1.f; }
                if (z1 > tau) { sp += z1; kp += 1.f; }
                if (z2 > tau) { sp += z2; kp += 1.f; }
                if (z3 > tau) { sp += z3; kp += 1.f; }
                sp = wsum(sp); kp = wsum(kp);
                float tn = (sp - 1.0f) / kp;
                if (tn == tau) break;
                tau = tn;
            }
            if (lane == 0) sTau[row] = tau + mx;
            float m0 = fmaxf(z0 - tau, 0.f), m1 = fmaxf(z1 - tau, 0.f);
            float m2 = fmaxf(z2 - tau, 0.f), m3 = fmaxf(z3 - tau, 0.f);
            mloss += m0 * __logf(m0 + 1e-10f) + m1 * __logf(m1 + 1e-10f)
                   + m2 * __logf(m2 + 1e-10f) + m3 * __logf(m3 + 1e-10f);
            float2 xa = *(const float2*)(xnb + row * 128 + 2 * lane);
            float2 xb = *(const float2*)(xnb + row * 128 + 64 + 2 * lane);
            float v0 = m0 * xa.x, v1 = m1 * xa.y, v2 = m2 * xb.x, v3 = m3 * xb.y;
            uint32_t rb = (uint32_t)((row >> 3) * 1024 + (row & 7) * 128);
            uint32_t b0 = rb + 4 * lane;         b0 ^= (b0 >> 3) & 0x70;
            uint32_t b1 = rb + 16384 + 4 * lane; b1 ^= (b1 >> 3) & 0x70;
            __nv_bfloat16 h0 = __float2bfloat16(v0), h1 = __float2bfloat16(v1);
            __nv_bfloat16 h2 = __float2bfloat16(v2), h3 = __float2bfloat16(v3);
            __nv_bfloat162 p01; p01.x = h0; p01.y = h1;
            __nv_bfloat162 p23; p23.x = h2; p23.y = h3;
            *(__nv_bfloat162*)(smem + OFF_A + b0) = p01;
            *(__nv_bfloat162*)(smem + OFF_A + b1) = p23;
            __nv_bfloat162 l01, l23;
            l01.x = __float2bfloat16(v0 - __bfloat162float(h0));
            l01.y = __float2bfloat16(v1 - __bfloat162float(h1));
            l23.x = __float2bfloat16(v2 - __bfloat162float(h2));
            l23.y = __float2bfloat16(v3 - __bfloat162float(h3));
            *(__nv_bfloat162*)(smem + OFF_A + 32768 + b0) = l01;
            *(__nv_bfloat162*)(smem + OFF_A + 32768 + b1) = l23;
        }
        __syncthreads();

        if (s < NSTEPS - 1) {
            run_phase<128, 0>(smem, sb, 6, g_wb + WB_E0 + (size_t)s * 6 * 16384,
                              encg0, encb0, 0, OFF_A, 0, w, lane, t, gatt_ch, nullptr);
            run_phase<192, 2>(smem, sb, 4, g_wb + WB_E1 + (size_t)s * 4 * 24576,
                              encg1, encb1, 64, OFF_H, s == 0, w, lane, t, gatt_ch, nullptr);
        }
        run_phase<128, 0>(smem, sb, 6, g_wb + WB_D0 + (size_t)s * 6 * 16384,
                          decg0, decb0, 0, OFF_A, 0, w, lane, t, gatt_ch, nullptr);
        run_phase<192, 1>(smem, sb, 2, g_wb + WB_D1 + (size_t)s * 2 * 24576,
                          decg1, decb1, 0, OFF_H, 0, w, lane, t, gatt_ch,
                          outp + ((size_t)s * BATCH + (size_t)chunk * 128) * 64);
    }

    mloss = wsum(mloss);
    if (lane == 0) atomicAdd(&g_mloss, mloss);
}

// ---------------- launch ----------------
extern "C" void kernel_launch(void* const* d_in, const int* in_sizes, int n_in,
                              void* d_out, int out_size) {
    const float* x     = (const float*)d_in[0];
    const float* ig    = (const float*)d_in[1];
    const float* ib    = (const float*)d_in[2];
    const float* encW0 = (const float*)d_in[3];
    const float* encg0 = (const float*)d_in[4];
    const float* encb0 = (const float*)d_in[5];
    const float* encW1 = (const float*)d_in[6];
    const float* encg1 = (const float*)d_in[7];
    const float* encb1 = (const float*)d_in[8];
    const float* decW0 = (const float*)d_in[9];
    const float* decg0 = (const float*)d_in[10];
    const float* decb0 = (const float*)d_in[11];
    const float* decW1 = (const float*)d_in[12];
    const float* decg1 = (const float*)d_in[13];
    const float* decb1 = (const float*)d_in[14];
    float* out = (float*)d_out;

    cudaFuncSetAttribute(tabnet_main, cudaFuncAttributeMaxDynamicSharedMemorySize, SMEM_BYTES);

    k_zero<<<1, 128>>>();
    k_stats<<<BATCH / 128, 128>>>(x);
    k_xn<<<(BATCH * 128 / 4) / 256, 256>>>(x, ig, ib);
    k_wpack<<<54, 256>>>(encW0, encW1, decW0, decW1);
    tabnet_main<<<BATCH / 128, 512, SMEM_BYTES>>>(
        encg0, encb0, encg1, encb1,
        decg0, decb0, decg1, decb1, out);
    k_fin<<<1, 1>>>(out);
}

// round 14
// speedup vs baseline: 2.6844x; 1.5138x over previous
#include <cuda_runtime.h>
#include <cuda_fp16.h>
#include <cstdint>

#define BATCH   32768
#define NSTEPS  3
#define BN_EPS  1e-5f
#define FULLM   0xffffffffu

union F2U { unsigned long long u; float2 f; };

// ---------------- SMEM layout (byte offsets, 1024-aligned) ----------------
#define OFF_A     0        // masked_x fp16 [128 x 128]  = 32768
#define OFF_H     32768    // h1 fp16 [128 x 192]        = 49152
#define OFF_B     81920    // B tile fp16 [64 x K]       <= 24576
#define OFF_TAU   106496   // 128 floats
#define OFF_STATS 107008   // float4[256] = 4096 B
#define OFF_CST   111104   // float2[64] = 512 B
#define SMEM_BYTES 111616

// ---------------- device scratch ----------------
__device__ float g_sum[128];
__device__ float g_sumsq[128];
__device__ float g_mloss;
__device__ float g_xn[(size_t)BATCH * 128];
__device__ float g_att[(size_t)BATCH * 128];
__device__ __align__(16) __half g_wb[516096];   // pre-swizzled fp16 weight images

#define WB_E0 0
#define WB_D0 147456
#define WB_E1 294912
#define WB_D1 442368

// ---------------- helpers ----------------
__device__ __forceinline__ float wsum(float v) {
#pragma unroll
    for (int o = 16; o > 0; o >>= 1) v += __shfl_xor_sync(FULLM, v, o);
    return v;
}
__device__ __forceinline__ float wmax(float v) {
#pragma unroll
    for (int o = 16; o > 0; o >>= 1) v = fmaxf(v, __shfl_xor_sync(FULLM, v, o));
    return v;
}
__device__ __forceinline__ float sigf(float x) { return 1.0f / (1.0f + __expf(-x)); }

__device__ __forceinline__ uint32_t smem_to_u32(const void* p) {
    uint32_t a;
    asm("{ .reg .u64 t; cvta.to.shared.u64 t, %1; cvt.u32.u64 %0, t; }" : "=r"(a) : "l"(p));
    return a;
}

#define LDM_X4(r, a) \
    asm volatile("ldmatrix.sync.aligned.m8n8.x4.shared.b16 {%0,%1,%2,%3}, [%4];" \
        : "=r"((r)[0]), "=r"((r)[1]), "=r"((r)[2]), "=r"((r)[3]) : "r"(a))
#define MMA16816(c, a, b0v, b1v) \
    asm volatile("mma.sync.aligned.m16n8k16.row.col.f32.f16.f16.f32 " \
        "{%0,%1,%2,%3}, {%4,%5,%6,%7}, {%8,%9}, {%0,%1,%2,%3};" \
        : "+f"((c)[0]), "+f"((c)[1]), "+f"((c)[2]), "+f"((c)[3]) \
        : "r"((a)[0]), "r"((a)[1]), "r"((a)[2]), "r"((a)[3]), "r"(b0v), "r"(b1v))

// ---------------- phase: prefetched B -> HMMA fp16 -> GBN+GLU epilogue ----------------
// 16 warps: rw = w&7 owns rows 16rw..16rw+15; h = w>>3 owns a-cols [16h,16h+16) + gates.
// MODE 0: GLU out (fp16) -> h1 image; MODE 1: sigmoid -> gmem out; MODE 2: att update in gmem
template<int K, int MODE>
__device__ void run_phase(char* smem, uint32_t sb, int ntiles,
                          const __half* __restrict__ imgs,
                          const float* __restrict__ gam, const float* __restrict__ bet,
                          int pair0, uint32_t aoff, int first,
                          int w, int lane, int t,
                          float* __restrict__ gatt_ch, float* __restrict__ outb)
{
    constexpr int N16 = 8 * K;                 // uint4 per tile image
    constexpr int NPF = N16 / 512;
    const float*  sTau = (const float*)(smem + OFF_TAU);
    float4* sStats = (float4*)(smem + OFF_STATS);
    float2* sCst   = (float2*)(smem + OFF_CST);

    const int rw = w & 7, h = w >> 3;

    // ---- A addressing ----
    const int lrow = (lane & 7) + ((lane >> 3) & 1) * 8;
    const int row16 = 16 * rw + lrow;
    const uint32_t arow = sb + aoff + (uint32_t)((row16 >> 3) * 1024 + (row16 & 7) * 128);
    const uint32_t axor = (uint32_t)((row16 & 7) << 4);
    const int ka_off = (lane >> 4) * 8;

    // ---- B addressing: two n16 groups (a-cols & gates) ----
    const int bsub = ((lane >> 4) << 3) + (lane & 7);      // 0..15
    const int bk   = ((lane >> 3) & 1) * 8;
    const int nA = 16 * h + bsub;
    const int nG = 32 + 16 * h + bsub;
    const uint32_t browA = sb + (uint32_t)OFF_B + (uint32_t)((nA >> 3) * 1024 + (nA & 7) * 128);
    const uint32_t browG = sb + (uint32_t)OFF_B + (uint32_t)((nG >> 3) * 1024 + (nG & 7) * 128);
    const uint32_t bxor = (uint32_t)((nA & 7) << 4);       // nG&7 == nA&7

    const uint4* wsrc = (const uint4*)imgs;
    uint4* bdst = (uint4*)(smem + OFF_B);

    // tile 0 B copy
    for (int ii = t; ii < N16; ii += 512) bdst[ii] = __ldg(wsrc + ii);
    __syncthreads();

#pragma unroll 1
    for (int i = 0; i < ntiles; i++) {
        // ---- prefetch next tile's B image into registers ----
        uint4 pf[NPF];
        if (i + 1 < ntiles) {
            const uint4* s = wsrc + (size_t)(i + 1) * N16;
#pragma unroll
            for (int n = 0; n < NPF; n++) pf[n] = __ldg(s + t + n * 512);
        }

        // ---- HMMA mainloop: acc[0..1] = a-col n8 groups, acc[2..3] = gate groups ----
        float acc[4][4];
#pragma unroll
        for (int g = 0; g < 4; g++)
#pragma unroll
            for (int c = 0; c < 4; c++) acc[g][c] = 0.0f;

#pragma unroll
        for (int ks = 0; ks < K / 16; ks++) {
            const int ka = ks * 16 + ka_off;
            const uint32_t aterm = (uint32_t)((ka >> 6) * 16384) + ((uint32_t)((ka & 63) * 2) ^ axor);
            const int kb = ks * 16 + bk;
            const uint32_t bterm = (uint32_t)((kb >> 6) * 8192) + ((uint32_t)((kb & 63) * 2) ^ bxor);
            uint32_t av[4], ba[4], bg[4];
            LDM_X4(av, arow + aterm);
            LDM_X4(ba, browA + bterm);
            LDM_X4(bg, browG + bterm);
#pragma unroll
            for (int g = 0; g < 2; g++) {
                MMA16816(acc[g],     av, ba[2 * g], ba[2 * g + 1]);
                MMA16816(acc[2 + g], av, bg[2 * g], bg[2 * g + 1]);
            }
        }

        const int pairB = pair0 + 32 * i;

        // ---- Ghost-BN stats: butterfly over 16 rows, combine across 8 row-warps ----
#pragma unroll
        for (int g = 0; g < 4; g++) {
            F2U S, Q;
            S.f.x = acc[g][0] + acc[g][2];
            S.f.y = acc[g][1] + acc[g][3];
            Q.f.x = acc[g][0] * acc[g][0] + acc[g][2] * acc[g][2];
            Q.f.y = acc[g][1] * acc[g][1] + acc[g][3] * acc[g][3];
#pragma unroll
            for (int o = 4; o <= 16; o <<= 1) {
                unsigned long long ss = __shfl_xor_sync(FULLM, S.u, o);
                unsigned long long qq = __shfl_xor_sync(FULLM, Q.u, o);
                asm("add.rn.f32x2 %0, %0, %1;" : "+l"(S.u) : "l"(ss));
                asm("add.rn.f32x2 %0, %0, %1;" : "+l"(Q.u) : "l"(qq));
            }
            if ((lane >> 2) == 0) {
                const int cbase = (g < 2) ? (16 * h + 8 * g) : (32 + 16 * h + 8 * (g - 2));
                const int pairid = (cbase >> 1) + (lane & 3);
                sStats[pairid * 8 + rw] = make_float4(S.f.x, S.f.y, Q.f.x, Q.f.y);
            }
        }
        __syncthreads();   // all warps done with mainloop (B reads) + stats writes

        // ---- commit prefetched B (overlapped with BN-constant stage) ----
        if (i + 1 < ntiles) {
#pragma unroll
            for (int n = 0; n < NPF; n++) bdst[t + n * 512] = pf[n];
        }
        if (t < 64) {
            const int c = t;
            float s = 0.f, q = 0.f;
#pragma unroll
            for (int r8 = 0; r8 < 8; r8++) {
                float4 v = sStats[(c >> 1) * 8 + r8];
                s += (c & 1) ? v.y : v.x;
                q += (c & 1) ? v.w : v.z;
            }
            float mean = s * (1.f / 128.f);
            float var  = q * (1.f / 128.f) - mean * mean;
            float rstd = rsqrtf(var + BN_EPS);
            const int j = (c < 32) ? (pairB + c) : (pairB + (c - 32) + 192);
            float ga = __ldg(gam + j) * rstd;
            sCst[c] = make_float2(ga, __ldg(bet + j) - mean * ga);
        }
        __syncthreads();

        // ---- apply: GLU (gate group register-local: acc[2+g]) + mode write ----
        const int c0 = 2 * (lane & 3);
        const int r0 = 16 * rw + (lane >> 2), r1 = r0 + 8;
#pragma unroll
        for (int g = 0; g < 2; g++) {
            const int ca = 16 * h + 8 * g + c0;
            float2 k0 = sCst[ca], k1 = sCst[ca + 1];
            float2 q0 = sCst[ca + 32], q1 = sCst[ca + 33];
            float glu00 = (acc[g][0] * k0.x + k0.y) * sigf(acc[2 + g][0] * q0.x + q0.y);
            float glu01 = (acc[g][1] * k1.x + k1.y) * sigf(acc[2 + g][1] * q1.x + q1.y);
            float glu10 = (acc[g][2] * k0.x + k0.y) * sigf(acc[2 + g][2] * q0.x + q0.y);
            float glu11 = (acc[g][3] * k1.x + k1.y) * sigf(acc[2 + g][3] * q1.x + q1.y);
            const int jb = pairB + ca;

            if (MODE == 0) {
                const uint32_t jt = (uint32_t)((jb >> 6) * 16 * 1024) + ((uint32_t)((jb & 63) * 2));
                uint32_t o0 = ((r0 >> 3) * 1024 + (r0 & 7) * 128) + (jt ^ ((uint32_t)(r0 & 7) << 4));
                uint32_t o1 = ((r1 >> 3) * 1024 + (r1 & 7) * 128) + (jt ^ ((uint32_t)(r1 & 7) << 4));
                __half2 p0; p0.x = __float2half(glu00); p0.y = __float2half(glu01);
                __half2 p1; p1.x = __float2half(glu10); p1.y = __float2half(glu11);
                *(__half2*)(smem + OFF_H + o0) = p0;
                *(__half2*)(smem + OFF_H + o1) = p1;
            } else if (MODE == 1) {
                *(float2*)(outb + (size_t)r0 * 64 + jb) = make_float2(sigf(glu00), sigf(glu01));
                *(float2*)(outb + (size_t)r1 * 64 + jb) = make_float2(sigf(glu10), sigf(glu11));
            } else {  // MODE 2: att update
                const int ac = jb - 64;
                float2* ap0 = (float2*)(gatt_ch + r0 * 128 + ac);
                float2* ap1 = (float2*)(gatt_ch + r1 * 128 + ac);
                float2 o0 = first ? make_float2(1.f, 1.f) : *ap0;
                float2 o1 = first ? make_float2(1.f, 1.f) : *ap1;
                float t0 = sTau[r0], t1 = sTau[r1];
                *ap0 = make_float2(1.3f * sigf(glu00) * (1.f - fmaxf(o0.x - t0, 0.f)),
                                   1.3f * sigf(glu01) * (1.f - fmaxf(o0.y - t0, 0.f)));
                *ap1 = make_float2(1.3f * sigf(glu10) * (1.f - fmaxf(o1.x - t1, 0.f)),
                                   1.3f * sigf(glu11) * (1.f - fmaxf(o1.y - t1, 0.f)));
            }
        }
        // next mainloop reads B (committed before the bar above); apply writes
        // H/gmem which no concurrent mainloop reads -> no extra barrier needed.
    }
    __syncthreads();
}

// ---------------- pre/post kernels ----------------
__global__ void k_zero() {
    int t = threadIdx.x;
    if (t < 128) { g_sum[t] = 0.0f; g_sumsq[t] = 0.0f; }
    if (t == 0) g_mloss = 0.0f;
}
__global__ void k_stats(const float* __restrict__ x) {
    const int col = threadIdx.x;
    const int rb  = blockIdx.x * 128;
    float s = 0.0f, sq = 0.0f;
#pragma unroll 4
    for (int r = 0; r < 128; r++) {
        float v = x[(size_t)(rb + r) * 128 + col];
        s += v; sq = fmaf(v, v, sq);
    }
    atomicAdd(&g_sum[col], s);
    atomicAdd(&g_sumsq[col], sq);
}
__global__ void k_xn(const float* __restrict__ x,
                     const float* __restrict__ gam, const float* __restrict__ bet) {
    const int i4 = blockIdx.x * blockDim.x + threadIdx.x;
    const int c4 = (i4 & 31) << 2;
    float4 xv = ((const float4*)x)[i4];
    float o[4] = {xv.x, xv.y, xv.z, xv.w};
    const float inv = 1.0f / (float)BATCH;
#pragma unroll
    for (int j = 0; j < 4; j++) {
        const int c = c4 + j;
        float mean = g_sum[c] * inv;
        float var  = g_sumsq[c] * inv - mean * mean;
        o[j] = (o[j] - mean) * rsqrtf(var + BN_EPS) * gam[c] + bet[c];
    }
    ((float4*)g_xn)[i4] = make_float4(o[0], o[1], o[2], o[3]);
}

// Build fp16 B-tile SMEM images, blocked-atom SW128 swizzled. 54 blocks.
__global__ void k_wpack(const float* __restrict__ e0, const float* __restrict__ e1,
                        const float* __restrict__ d0, const float* __restrict__ d1) {
    int b = blockIdx.x;
    const float* W; int K, s, tile, base, pair0;
    if (b < 18)      { W = e0; K = 128; s = b / 6;      tile = b % 6;      base = WB_E0 + (s*6+tile)*8192;  pair0 = 32*tile; }
    else if (b < 36) { W = d0; K = 128; s = (b-18)/6;   tile = (b-18)%6;   base = WB_D0 + (s*6+tile)*8192;  pair0 = 32*tile; }
    else if (b < 48) { W = e1; K = 192; s = (b-36)/4;   tile = (b-36)%4;   base = WB_E1 + (s*4+tile)*12288; pair0 = 64+32*tile; }
    else             { W = d1; K = 192; s = (b-48)/2;   tile = (b-48)%2;   base = WB_D1 + (s*2+tile)*12288; pair0 = 32*tile; }
    const float* Ws = W + (size_t)s * 384 * K;
    __half* img = g_wb + base;
    const int tot = 64 * K;
    for (int idx = threadIdx.x; idx < tot; idx += blockDim.x) {
        int n = idx / K, k = idx % K;
        int j = pair0 + (n < 32 ? n : n - 32 + 192);
        float v = __ldg(Ws + (size_t)j * K + k);
        uint32_t bo = (uint32_t)(((n >> 3) + (k >> 6) * 8) * 1024 + (n & 7) * 128 + (k & 63) * 2);
        bo ^= (bo >> 3) & 0x70;
        img[bo >> 1] = __float2half(v);
    }
}

__global__ void k_fin(float* __restrict__ outp) {
    outp[(size_t)NSTEPS * BATCH * 64] = g_mloss * (1.0f / ((float)BATCH * (float)NSTEPS));
}

// ---------------- main fused kernel: one CTA = one 128-row GBN chunk ----------------
__global__ void __launch_bounds__(512, 2) tabnet_main(
    const float* __restrict__ encg0, const float* __restrict__ encb0,
    const float* __restrict__ encg1, const float* __restrict__ encb1,
    const float* __restrict__ decg0, const float* __restrict__ decb0,
    const float* __restrict__ decg1, const float* __restrict__ decb1,
    float* __restrict__ outp)
{
    extern __shared__ char smem[];
    uint32_t sb = smem_to_u32(smem);
    const int t = threadIdx.x, lane = t & 31, w = t >> 5;
    const int chunk = blockIdx.x;
    float* gatt_ch = g_att + (size_t)chunk * 16384;
    const float* xnb = g_xn + (size_t)chunk * 16384;
    float* sTau = (float*)(smem + OFF_TAU);

    float mloss = 0.0f;

    for (int s = 0; s < NSTEPS; s++) {
        // ---- sparsemax (Michelot, exact) + mask + A image build (fp16) ----
        for (int rr = 0; rr < 8; rr++) {
            const int row = w * 8 + rr;
            float z0, z1, z2, z3;
            if (s == 0) { z0 = z1 = z2 = z3 = 1.0f; }
            else {
                float2 za = *(const float2*)(gatt_ch + row * 128 + 2 * lane);
                float2 zb = *(const float2*)(gatt_ch + row * 128 + 64 + 2 * lane);
                z0 = za.x; z1 = za.y; z2 = zb.x; z3 = zb.y;
            }
            float mx = wmax(fmaxf(fmaxf(z0, z1), fmaxf(z2, z3)));
            z0 -= mx; z1 -= mx; z2 -= mx; z3 -= mx;
            float tau = (wsum(z0 + z1 + z2 + z3) - 1.0f) * (1.0f / 128.0f);
            for (int it = 0; it < 32; it++) {
                float sp = 0.f, kp = 0.f;
                if (z0 > tau) { sp += z0; kp += 1.f; }
                if (z1 > tau) { sp += z1; kp += 1.f; }
                if (z2 > tau) { sp += z2; kp += 1.f; }
                if (z3 > tau) { sp += z3; kp += 1.f; }
                sp = wsum(sp); kp = wsum(kp);
                float tn = (sp - 1.0f) / kp;
                if (tn == tau) break;
                tau = tn;
            }
            if (lane == 0) sTau[row] = tau + mx;
            float m0 = fmaxf(z0 - tau, 0.f), m1 = fmaxf(z1 - tau, 0.f);
            float m2 = fmaxf(z2 - tau, 0.f), m3 = fmaxf(z3 - tau, 0.f);
            mloss += m0 * __logf(m0 + 1e-10f) + m1 * __logf(m1 + 1e-10f)
                   + m2 * __logf(m2 + 1e-10f) + m3 * __logf(m3 + 1e-10f);
            float2 xa = *(const float2*)(xnb + row * 128 + 2 * lane);
            float2 xb = *(const float2*)(xnb + row * 128 + 64 + 2 * lane);
            uint32_t rb = (uint32_t)((row >> 3) * 1024 + (row & 7) * 128);
            uint32_t b0 = rb + 4 * lane;         b0 ^= (b0 >> 3) & 0x70;
            uint32_t b1 = rb + 16384 + 4 * lane; b1 ^= (b1 >> 3) & 0x70;
            __half2 p01; p01.x = __float2half(m0 * xa.x); p01.y = __float2half(m1 * xa.y);
            __half2 p23; p23.x = __float2half(m2 * xb.x); p23.y = __float2half(m3 * xb.y);
            *(__half2*)(smem + OFF_A + b0) = p01;
            *(__half2*)(smem + OFF_A + b1) = p23;
        }
        __syncthreads();

        if (s < NSTEPS - 1) {
            run_phase<128, 0>(smem, sb, 6, g_wb + WB_E0 + (size_t)s * 6 * 8192,
                              encg0, encb0, 0, OFF_A, 0, w, lane, t, gatt_ch, nullptr);
            run_phase<192, 2>(smem, sb, 4, g_wb + WB_E1 + (size_t)s * 4 * 12288,
                              encg1, encb1, 64, OFF_H, s == 0, w, lane, t, gatt_ch, nullptr);
        }
        run_phase<128, 0>(smem, sb, 6, g_wb + WB_D0 + (size_t)s * 6 * 8192,
                          decg0, decb0, 0, OFF_A, 0, w, lane, t, gatt_ch, nullptr);
        run_phase<192, 1>(smem, sb, 2, g_wb + WB_D1 + (size_t)s * 2 * 12288,
                          decg1, decb1, 0, OFF_H, 0, w, lane, t, gatt_ch,
                          outp + ((size_t)s * BATCH + (size_t)chunk * 128) * 64);
    }

    mloss = wsum(mloss);
    if (lane == 0) atomicAdd(&g_mloss, mloss);
}

// ---------------- launch ----------------
extern "C" void kernel_launch(void* const* d_in, const int* in_sizes, int n_in,
                              void* d_out, int out_size) {
    const float* x     = (const float*)d_in[0];
    const float* ig    = (const float*)d_in[1];
    const float* ib    = (const float*)d_in[2];
    const float* encW0 = (const float*)d_in[3];
    const float* encg0 = (const float*)d_in[4];
    const float* encb0 = (const float*)d_in[5];
    const float* encW1 = (const float*)d_in[6];
    const float* encg1 = (const float*)d_in[7];
    const float* encb1 = (const float*)d_in[8];
    const float* decW0 = (const float*)d_in[9];
    const float* decg0 = (const float*)d_in[10];
    const float* decb0 = (const float*)d_in[11];
    const float* decW1 = (const float*)d_in[12];
    const float* decg1 = (const float*)d_in[13];
    const float* decb1 = (const float*)d_in[14];
    float* out = (float*)d_out;

    cudaFuncSetAttribute(tabnet_main, cudaFuncAttributeMaxDynamicSharedMemorySize, SMEM_BYTES);

    k_zero<<<1, 128>>>();
    k_stats<<<BATCH / 128, 128>>>(x);
    k_xn<<<(BATCH * 128 / 4) / 256, 256>>>(x, ig, ib);
    k_wpack<<<54, 256>>>(encW0, encW1, decW0, decW1);
    tabnet_main<<<BATCH / 128, 512, SMEM_BYTES>>>(
        encg0, encb0, encg1, encb1,
        decg0, decb0, decg1, decb1, out);
    k_fin<<<1, 1>>>(out);
}

// round 15
// speedup vs baseline: 3.0821x; 1.1482x over previous
#include <cuda_runtime.h>
#include <cuda_fp16.h>
#include <cstdint>

#define BATCH   32768
#define NSTEPS  3
#define BN_EPS  1e-5f
#define FULLM   0xffffffffu

union F2U { unsigned long long u; float2 f; };

// ---------------- SMEM layout (byte offsets, 1024-aligned) ----------------
#define OFF_A     0        // masked_x fp16 [128 x 128]  = 32768
#define OFF_H     32768    // h1 fp16 [128 x 192]        = 49152
#define OFF_B     81920    // B tile fp16 [64 x K]       <= 24576
#define OFF_TAU   106496   // 128 floats = 512
#define OFF_STATS 107008   // float4[128] = 2048
#define OFF_CST   109056   // float2[64] = 512
#define SMEM_BYTES 109568

// ---------------- device scratch ----------------
__device__ float g_sum[128];
__device__ float g_sumsq[128];
__device__ float g_mloss;
__device__ float g_xn[(size_t)BATCH * 128];
__device__ float g_att[(size_t)BATCH * 128];
__device__ __align__(16) __half g_wb[516096];   // pre-swizzled fp16 weight images

#define WB_E0 0
#define WB_D0 147456
#define WB_E1 294912
#define WB_D1 442368

// ---------------- helpers ----------------
__device__ __forceinline__ float wsum(float v) {
#pragma unroll
    for (int o = 16; o > 0; o >>= 1) v += __shfl_xor_sync(FULLM, v, o);
    return v;
}
__device__ __forceinline__ float wmax(float v) {
#pragma unroll
    for (int o = 16; o > 0; o >>= 1) v = fmaxf(v, __shfl_xor_sync(FULLM, v, o));
    return v;
}
__device__ __forceinline__ float sigf(float x) { return 1.0f / (1.0f + __expf(-x)); }

__device__ __forceinline__ uint32_t smem_to_u32(const void* p) {
    uint32_t a;
    asm("{ .reg .u64 t; cvta.to.shared.u64 t, %1; cvt.u32.u64 %0, t; }" : "=r"(a) : "l"(p));
    return a;
}

#define LDM_X4(r, a) \
    asm volatile("ldmatrix.sync.aligned.m8n8.x4.shared.b16 {%0,%1,%2,%3}, [%4];" \
        : "=r"((r)[0]), "=r"((r)[1]), "=r"((r)[2]), "=r"((r)[3]) : "r"(a))
#define MMA16816(c, a, b0v, b1v) \
    asm volatile("mma.sync.aligned.m16n8k16.row.col.f32.f16.f16.f32 " \
        "{%0,%1,%2,%3}, {%4,%5,%6,%7}, {%8,%9}, {%0,%1,%2,%3};" \
        : "+f"((c)[0]), "+f"((c)[1]), "+f"((c)[2]), "+f"((c)[3]) \
        : "r"((a)[0]), "r"((a)[1]), "r"((a)[2]), "r"((a)[3]), "r"(b0v), "r"(b1v))

// ---------------- phase: prefetched B -> HMMA fp16 -> GBN+GLU epilogue ----------------
// 8 warps: rw = w&3 owns rows 32rw..32rw+31; h = w>>2 owns a-cols [16h,16h+16) + gates.
// MODE 0: GLU out (fp16) -> h1 image; MODE 1: sigmoid -> gmem out; MODE 2: att update in gmem
template<int K, int MODE>
__device__ void run_phase(char* smem, uint32_t sb, int ntiles,
                          const __half* __restrict__ imgs,
                          const float* __restrict__ gam, const float* __restrict__ bet,
                          int pair0, uint32_t aoff, int first,
                          int w, int lane, int t,
                          float* __restrict__ gatt_ch, float* __restrict__ outb)
{
    constexpr int N16 = 8 * K;                 // uint4 per tile image
    constexpr int NPF = N16 / 256;
    const float*  sTau = (const float*)(smem + OFF_TAU);
    float4* sStats = (float4*)(smem + OFF_STATS);
    float2* sCst   = (float2*)(smem + OFF_CST);

    const int rw = w & 3, h = w >> 2;

    // ---- A addressing: two 16-row tiles (32rw.., 32rw+16..) ----
    const int lrow = (lane & 7) + ((lane >> 3) & 1) * 8;
    const int row16 = 32 * rw + lrow;
    const uint32_t arow0 = sb + aoff + (uint32_t)((row16 >> 3) * 1024 + (row16 & 7) * 128);
    const uint32_t axor = (uint32_t)((row16 & 7) << 4);
    const int ka_off = (lane >> 4) * 8;

    // ---- B addressing: 16 a-cols + 16 gate-cols ----
    const int bsub = ((lane >> 4) << 3) + (lane & 7);      // 0..15
    const int bk   = ((lane >> 3) & 1) * 8;
    const int nA = 16 * h + bsub;
    const int nG = 32 + 16 * h + bsub;
    const uint32_t browA = sb + (uint32_t)OFF_B + (uint32_t)((nA >> 3) * 1024 + (nA & 7) * 128);
    const uint32_t browG = sb + (uint32_t)OFF_B + (uint32_t)((nG >> 3) * 1024 + (nG & 7) * 128);
    const uint32_t bxor = (uint32_t)((nA & 7) << 4);       // nG&7 == nA&7

    const uint4* wsrc = (const uint4*)imgs;
    uint4* bdst = (uint4*)(smem + OFF_B);

    // tile 0 B copy
    for (int ii = t; ii < N16; ii += 256) bdst[ii] = __ldg(wsrc + ii);
    __syncthreads();

#pragma unroll 1
    for (int i = 0; i < ntiles; i++) {
        // ---- prefetch next tile's B image into registers ----
        uint4 pf[NPF];
        if (i + 1 < ntiles) {
            const uint4* s = wsrc + (size_t)(i + 1) * N16;
#pragma unroll
            for (int n = 0; n < NPF; n++) pf[n] = __ldg(s + t + n * 256);
        }

        // ---- HMMA mainloop: acc[mt][cg]: mt = 16-row tile, cg 0/1 = a n8-groups, 2/3 = gates ----
        float acc[2][4][4];
#pragma unroll
        for (int mt = 0; mt < 2; mt++)
#pragma unroll
            for (int g = 0; g < 4; g++)
#pragma unroll
                for (int c = 0; c < 4; c++) acc[mt][g][c] = 0.0f;

#pragma unroll
        for (int ks = 0; ks < K / 16; ks++) {
            const int ka = ks * 16 + ka_off;
            const uint32_t aterm = (uint32_t)((ka >> 6) * 16384) + ((uint32_t)((ka & 63) * 2) ^ axor);
            const int kb = ks * 16 + bk;
            const uint32_t bterm = (uint32_t)((kb >> 6) * 8192) + ((uint32_t)((kb & 63) * 2) ^ bxor);
            uint32_t av0[4], av1[4], ba[4], bg[4];
            LDM_X4(av0, arow0 + aterm);
            LDM_X4(av1, arow0 + 2048 + aterm);
            LDM_X4(ba, browA + bterm);
            LDM_X4(bg, browG + bterm);
#pragma unroll
            for (int g = 0; g < 2; g++) {
                MMA16816(acc[0][g],     av0, ba[2 * g], ba[2 * g + 1]);
                MMA16816(acc[1][g],     av1, ba[2 * g], ba[2 * g + 1]);
                MMA16816(acc[0][2 + g], av0, bg[2 * g], bg[2 * g + 1]);
                MMA16816(acc[1][2 + g], av1, bg[2 * g], bg[2 * g + 1]);
            }
        }

        const int pairB = pair0 + 32 * i;

        // ---- Ghost-BN stats: 32 rows in-warp, combine across 4 row-warps ----
#pragma unroll
        for (int g = 0; g < 4; g++) {
            F2U S, Q;
            S.f.x = acc[0][g][0] + acc[0][g][2] + acc[1][g][0] + acc[1][g][2];
            S.f.y = acc[0][g][1] + acc[0][g][3] + acc[1][g][1] + acc[1][g][3];
            Q.f.x = acc[0][g][0]*acc[0][g][0] + acc[0][g][2]*acc[0][g][2]
                  + acc[1][g][0]*acc[1][g][0] + acc[1][g][2]*acc[1][g][2];
            Q.f.y = acc[0][g][1]*acc[0][g][1] + acc[0][g][3]*acc[0][g][3]
                  + acc[1][g][1]*acc[1][g][1] + acc[1][g][3]*acc[1][g][3];
#pragma unroll
            for (int o = 4; o <= 16; o <<= 1) {
                unsigned long long ss = __shfl_xor_sync(FULLM, S.u, o);
                unsigned long long qq = __shfl_xor_sync(FULLM, Q.u, o);
                asm("add.rn.f32x2 %0, %0, %1;" : "+l"(S.u) : "l"(ss));
                asm("add.rn.f32x2 %0, %0, %1;" : "+l"(Q.u) : "l"(qq));
            }
            if ((lane >> 2) == 0) {
                const int cbase = (g < 2) ? (16 * h + 8 * g) : (32 + 16 * h + 8 * (g - 2));
                const int pairid = (cbase >> 1) + (lane & 3);
                sStats[pairid * 4 + rw] = make_float4(S.f.x, S.f.y, Q.f.x, Q.f.y);
            }
        }
        __syncthreads();   // mainloop B reads + stats writes done

        // ---- commit prefetched B (overlapped with BN-constant stage) ----
        if (i + 1 < ntiles) {
#pragma unroll
            for (int n = 0; n < NPF; n++) bdst[t + n * 256] = pf[n];
        }
        if (t < 64) {
            const int c = t;
            float s = 0.f, q = 0.f;
#pragma unroll
            for (int r4 = 0; r4 < 4; r4++) {
                float4 v = sStats[(c >> 1) * 4 + r4];
                s += (c & 1) ? v.y : v.x;
                q += (c & 1) ? v.w : v.z;
            }
            float mean = s * (1.f / 128.f);
            float var  = q * (1.f / 128.f) - mean * mean;
            float rstd = rsqrtf(var + BN_EPS);
            const int j = (c < 32) ? (pairB + c) : (pairB + (c - 32) + 192);
            float ga = __ldg(gam + j) * rstd;
            sCst[c] = make_float2(ga, __ldg(bet + j) - mean * ga);
        }
        __syncthreads();

        // ---- apply: GLU (gate group register-local: acc[mt][2+g]) + mode write ----
        const int c0 = 2 * (lane & 3);
#pragma unroll
        for (int mt = 0; mt < 2; mt++) {
            const int r0 = 32 * rw + 16 * mt + (lane >> 2), r1 = r0 + 8;
#pragma unroll
            for (int g = 0; g < 2; g++) {
                const int ca = 16 * h + 8 * g + c0;
                float2 k0 = sCst[ca], k1 = sCst[ca + 1];
                float2 q0 = sCst[ca + 32], q1 = sCst[ca + 33];
                float glu00 = (acc[mt][g][0] * k0.x + k0.y) * sigf(acc[mt][2 + g][0] * q0.x + q0.y);
                float glu01 = (acc[mt][g][1] * k1.x + k1.y) * sigf(acc[mt][2 + g][1] * q1.x + q1.y);
                float glu10 = (acc[mt][g][2] * k0.x + k0.y) * sigf(acc[mt][2 + g][2] * q0.x + q0.y);
                float glu11 = (acc[mt][g][3] * k1.x + k1.y) * sigf(acc[mt][2 + g][3] * q1.x + q1.y);
                const int jb = pairB + ca;

                if (MODE == 0) {
                    const uint32_t jt = (uint32_t)((jb >> 6) * 16 * 1024) + ((uint32_t)((jb & 63) * 2));
                    uint32_t o0 = ((r0 >> 3) * 1024 + (r0 & 7) * 128) + (jt ^ ((uint32_t)(r0 & 7) << 4));
                    uint32_t o1 = ((r1 >> 3) * 1024 + (r1 & 7) * 128) + (jt ^ ((uint32_t)(r1 & 7) << 4));
                    __half2 p0; p0.x = __float2half(glu00); p0.y = __float2half(glu01);
                    __half2 p1; p1.x = __float2half(glu10); p1.y = __float2half(glu11);
                    *(__half2*)(smem + OFF_H + o0) = p0;
                    *(__half2*)(smem + OFF_H + o1) = p1;
                } else if (MODE == 1) {
                    *(float2*)(outb + (size_t)r0 * 64 + jb) = make_float2(sigf(glu00), sigf(glu01));
                    *(float2*)(outb + (size_t)r1 * 64 + jb) = make_float2(sigf(glu10), sigf(glu11));
                } else {  // MODE 2: att update
                    const int ac = jb - 64;
                    float2* ap0 = (float2*)(gatt_ch + r0 * 128 + ac);
                    float2* ap1 = (float2*)(gatt_ch + r1 * 128 + ac);
                    float2 o0 = first ? make_float2(1.f, 1.f) : *ap0;
                    float2 o1 = first ? make_float2(1.f, 1.f) : *ap1;
                    float t0 = sTau[r0], t1 = sTau[r1];
                    *ap0 = make_float2(1.3f * sigf(glu00) * (1.f - fmaxf(o0.x - t0, 0.f)),
                                       1.3f * sigf(glu01) * (1.f - fmaxf(o0.y - t0, 0.f)));
                    *ap1 = make_float2(1.3f * sigf(glu10) * (1.f - fmaxf(o1.x - t1, 0.f)),
                                       1.3f * sigf(glu11) * (1.f - fmaxf(o1.y - t1, 0.f)));
                }
            }
        }
        // next mainloop reads B (committed before the barrier above); apply writes
        // H/gmem which no concurrent mainloop reads -> no extra barrier needed.
    }
    __syncthreads();
}

// ---------------- pre/post kernels ----------------
__global__ void k_zero() {
    int t = threadIdx.x;
    if (t < 128) { g_sum[t] = 0.0f; g_sumsq[t] = 0.0f; }
    if (t == 0) g_mloss = 0.0f;
}
__global__ void k_stats(const float* __restrict__ x) {
    const int col = threadIdx.x;
    const int rb  = blockIdx.x * 128;
    float s = 0.0f, sq = 0.0f;
#pragma unroll 4
    for (int r = 0; r < 128; r++) {
        float v = x[(size_t)(rb + r) * 128 + col];
        s += v; sq = fmaf(v, v, sq);
    }
    atomicAdd(&g_sum[col], s);
    atomicAdd(&g_sumsq[col], sq);
}

// Build fp16 B-tile SMEM images, blocked-atom SW128 swizzled. 54 blocks.
__global__ void k_wpack(const float* __restrict__ e0, const float* __restrict__ e1,
                        const float* __restrict__ d0, const float* __restrict__ d1) {
    int b = blockIdx.x;
    const float* W; int K, s, tile, base, pair0;
    if (b < 18)      { W = e0; K = 128; s = b / 6;      tile = b % 6;      base = WB_E0 + (s*6+tile)*8192;  pair0 = 32*tile; }
    else if (b < 36) { W = d0; K = 128; s = (b-18)/6;   tile = (b-18)%6;   base = WB_D0 + (s*6+tile)*8192;  pair0 = 32*tile; }
    else if (b < 48) { W = e1; K = 192; s = (b-36)/4;   tile = (b-36)%4;   base = WB_E1 + (s*4+tile)*12288; pair0 = 64+32*tile; }
    else             { W = d1; K = 192; s = (b-48)/2;   tile = (b-48)%2;   base = WB_D1 + (s*2+tile)*12288; pair0 = 32*tile; }
    const float* Ws = W + (size_t)s * 384 * K;
    __half* img = g_wb + base;
    const int tot = 64 * K;
    for (int idx = threadIdx.x; idx < tot; idx += blockDim.x) {
        int n = idx / K, k = idx % K;
        int j = pair0 + (n < 32 ? n : n - 32 + 192);
        float v = __ldg(Ws + (size_t)j * K + k);
        uint32_t bo = (uint32_t)(((n >> 3) + (k >> 6) * 8) * 1024 + (n & 7) * 128 + (k & 63) * 2);
        bo ^= (bo >> 3) & 0x70;
        img[bo >> 1] = __float2half(v);
    }
}

__global__ void k_fin(float* __restrict__ outp) {
    outp[(size_t)NSTEPS * BATCH * 64] = g_mloss * (1.0f / ((float)BATCH * (float)NSTEPS));
}

// ---------------- main fused kernel: one CTA = one 128-row GBN chunk ----------------
__global__ void __launch_bounds__(256, 2) tabnet_main(
    const float* __restrict__ x_in,
    const float* __restrict__ ig, const float* __restrict__ ib,
    const float* __restrict__ encg0, const float* __restrict__ encb0,
    const float* __restrict__ encg1, const float* __restrict__ encb1,
    const float* __restrict__ decg0, const float* __restrict__ decb0,
    const float* __restrict__ decg1, const float* __restrict__ decb1,
    float* __restrict__ outp)
{
    extern __shared__ char smem[];
    uint32_t sb = smem_to_u32(smem);
    const int t = threadIdx.x, lane = t & 31, w = t >> 5;
    const int chunk = blockIdx.x;
    float* gatt_ch = g_att + (size_t)chunk * 16384;
    float* xnb = g_xn + (size_t)chunk * 16384;
    const float* xb_in = x_in + (size_t)chunk * 16384;
    float* sTau = (float*)(smem + OFF_TAU);

    // per-thread inline-BN constants for its 4 columns (cols 2lane, 2lane+1, 64+2lane, 65+2lane)
    float bga[4], bbb[4];
    {
        const float inv = 1.0f / (float)BATCH;
#pragma unroll
        for (int u = 0; u < 4; u++) {
            const int c = (u < 2) ? (2 * lane + u) : (64 + 2 * lane + (u - 2));
            float mean = g_sum[c] * inv;
            float var  = g_sumsq[c] * inv - mean * mean;
            float rstd = rsqrtf(var + BN_EPS);
            bga[u] = __ldg(ig + c) * rstd;
            bbb[u] = __ldg(ib + c) - mean * bga[u];
        }
    }

    float mloss = 0.0f;

    for (int s = 0; s < NSTEPS; s++) {
        // ---- sparsemax (Michelot, exact) + mask + A image build (fp16) ----
        for (int rr = 0; rr < 16; rr++) {
            const int row = w * 16 + rr;
            float z0, z1, z2, z3;
            if (s == 0) { z0 = z1 = z2 = z3 = 1.0f; }
            else {
                float2 za = *(const float2*)(gatt_ch + row * 128 + 2 * lane);
                float2 zb = *(const float2*)(gatt_ch + row * 128 + 64 + 2 * lane);
                z0 = za.x; z1 = za.y; z2 = zb.x; z3 = zb.y;
            }
            float mx = wmax(fmaxf(fmaxf(z0, z1), fmaxf(z2, z3)));
            z0 -= mx; z1 -= mx; z2 -= mx; z3 -= mx;
            float tau = (wsum(z0 + z1 + z2 + z3) - 1.0f) * (1.0f / 128.0f);
            for (int it = 0; it < 32; it++) {
                float sp = 0.f, kp = 0.f;
                if (z0 > tau) { sp += z0; kp += 1.f; }
                if (z1 > tau) { sp += z1; kp += 1.f; }
                if (z2 > tau) { sp += z2; kp += 1.f; }
                if (z3 > tau) { sp += z3; kp += 1.f; }
                sp = wsum(sp); kp = wsum(kp);
                float tn = (sp - 1.0f) / kp;
                if (tn == tau) break;
                tau = tn;
            }
            if (lane == 0) sTau[row] = tau + mx;
            float m0 = fmaxf(z0 - tau, 0.f), m1 = fmaxf(z1 - tau, 0.f);
            float m2 = fmaxf(z2 - tau, 0.f), m3 = fmaxf(z3 - tau, 0.f);
            mloss += m0 * __logf(m0 + 1e-10f) + m1 * __logf(m1 + 1e-10f)
                   + m2 * __logf(m2 + 1e-10f) + m3 * __logf(m3 + 1e-10f);
            float x0, x1, x2, x3;
            if (s == 0) {   // inline full-batch BN; persist xn for later steps
                float2 ra = *(const float2*)(xb_in + row * 128 + 2 * lane);
                float2 rb2 = *(const float2*)(xb_in + row * 128 + 64 + 2 * lane);
                x0 = ra.x * bga[0] + bbb[0];  x1 = ra.y * bga[1] + bbb[1];
                x2 = rb2.x * bga[2] + bbb[2]; x3 = rb2.y * bga[3] + bbb[3];
                *(float2*)(xnb + row * 128 + 2 * lane) = make_float2(x0, x1);
                *(float2*)(xnb + row * 128 + 64 + 2 * lane) = make_float2(x2, x3);
            } else {
                float2 xa = *(const float2*)(xnb + row * 128 + 2 * lane);
                float2 xc = *(const float2*)(xnb + row * 128 + 64 + 2 * lane);
                x0 = xa.x; x1 = xa.y; x2 = xc.x; x3 = xc.y;
            }
            uint32_t rbo = (uint32_t)((row >> 3) * 1024 + (row & 7) * 128);
            uint32_t b0 = rbo + 4 * lane;         b0 ^= (b0 >> 3) & 0x70;
            uint32_t b1 = rbo + 16384 + 4 * lane; b1 ^= (b1 >> 3) & 0x70;
            __half2 p01; p01.x = __float2half(m0 * x0); p01.y = __float2half(m1 * x1);
            __half2 p23; p23.x = __float2half(m2 * x2); p23.y = __float2half(m3 * x3);
            *(__half2*)(smem + OFF_A + b0) = p01;
            *(__half2*)(smem + OFF_A + b1) = p23;
        }
        __syncthreads();

        if (s < NSTEPS - 1) {
            run_phase<128, 0>(smem, sb, 6, g_wb + WB_E0 + (size_t)s * 6 * 8192,
                              encg0, encb0, 0, OFF_A, 0, w, lane, t, gatt_ch, nullptr);
            run_phase<192, 2>(smem, sb, 4, g_wb + WB_E1 + (size_t)s * 4 * 12288,
                              encg1, encb1, 64, OFF_H, s == 0, w, lane, t, gatt_ch, nullptr);
        }
        run_phase<128, 0>(smem, sb, 6, g_wb + WB_D0 + (size_t)s * 6 * 8192,
                          decg0, decb0, 0, OFF_A, 0, w, lane, t, gatt_ch, nullptr);
        run_phase<192, 1>(smem, sb, 2, g_wb + WB_D1 + (size_t)s * 2 * 12288,
                          decg1, decb1, 0, OFF_H, 0, w, lane, t, gatt_ch,
                          outp + ((size_t)s * BATCH + (size_t)chunk * 128) * 64);
    }

    mloss = wsum(mloss);
    if (lane == 0) atomicAdd(&g_mloss, mloss);
}

// ---------------- launch ----------------
extern "C" void kernel_launch(void* const* d_in, const int* in_sizes, int n_in,
                              void* d_out, int out_size) {
    const float* x     = (const float*)d_in[0];
    const float* ig    = (const float*)d_in[1];
    const float* ib    = (const float*)d_in[2];
    const float* encW0 = (const float*)d_in[3];
    const float* encg0 = (const float*)d_in[4];
    const float* encb0 = (const float*)d_in[5];
    const float* encW1 = (const float*)d_in[6];
    const float* encg1 = (const float*)d_in[7];
    const float* encb1 = (const float*)d_in[8];
    const float* decW0 = (const float*)d_in[9];
    const float* decg0 = (const float*)d_in[10];
    const float* decb0 = (const float*)d_in[11];
    const float* decW1 = (const float*)d_in[12];
    const float* decg1 = (const float*)d_in[13];
    const float* decb1 = (const float*)d_in[14];
    float* out = (float*)d_out;

    cudaFuncSetAttribute(tabnet_main, cudaFuncAttributeMaxDynamicSharedMemorySize, SMEM_BYTES);

    k_zero<<<1, 128>>>();
    k_stats<<<BATCH / 128, 128>>>(x);
    k_wpack<<<54, 256>>>(encW0, encW1, decW0, decW1);
    tabnet_main<<<BATCH / 128, 256, SMEM_BYTES>>>(
        x, ig, ib,
        encg0, encb0, encg1, encb1,
        decg0, decb0, decg1, decb1, out);
    k_fin<<<1, 1>>>(out);
}